// round 12
// baseline (speedup 1.0000x reference)
#include <cuda_runtime.h>
#include <cuda_fp16.h>
#include <math.h>
#include <stdint.h>

// Problem dims
#define BATCH 4
#define TSEQ  1024
#define BT    4096
#define DMODEL 1024
#define NE    8
#define FF    4096
#define CAP   9216
#define NTILES 72

// ---------------- static device scratch ----------------
__device__ float g_x2 [BT * DMODEL];
__device__ int   g_eidx[BT * 2];
__device__ float g_wts [BT * 2];
__device__ int   g_stok[CAP];          // slot -> token (-1 = padding)
__device__ float g_sw  [CAP];          // slot -> combine weight
__device__ int   g_tile_e[NTILES];

// fp16 split scratch
__device__ __half g_aHi [BT * DMODEL];
__device__ __half g_aLo [BT * DMODEL];
__device__ __half g_qkvHi[BT * 3 * DMODEL];
__device__ __half g_qkvLo[BT * 3 * DMODEL];
__device__ __half g_wHi [NE * FF * DMODEL];
__device__ __half g_wLo [NE * FF * DMODEL];
__device__ __half g_hidHi[CAP * FF];
__device__ __half g_hidLo[CAP * FF];

__device__ __forceinline__ float gelu_f(float v) {
    return 0.5f * v * (1.0f + erff(v * 0.70710678118654752f));
}

// ---------------- PTX helpers ----------------
__device__ __forceinline__ uint32_t smem_u32(const void* p) {
    uint32_t a;
    asm("{ .reg .u64 t; cvta.to.shared.u64 t, %1; cvt.u32.u64 %0, t; }" : "=r"(a) : "l"(p));
    return a;
}
__device__ __forceinline__ void cpa16(uint32_t dst, const void* src) {
    asm volatile("cp.async.cg.shared.global [%0], [%1], 16;" :: "r"(dst), "l"(src));
}
__device__ __forceinline__ void cp_commit() { asm volatile("cp.async.commit_group;" ::: "memory"); }
template<int NPEND> __device__ __forceinline__ void cp_wait() {
    asm volatile("cp.async.wait_group %0;" :: "n"(NPEND) : "memory");
}
__device__ __forceinline__ void ldm_x4(uint32_t* r, uint32_t a) {
    asm volatile("ldmatrix.sync.aligned.m8n8.x4.shared.b16 {%0,%1,%2,%3}, [%4];"
        : "=r"(r[0]), "=r"(r[1]), "=r"(r[2]), "=r"(r[3]) : "r"(a));
}
__device__ __forceinline__ void ldm_x4t(uint32_t* r, uint32_t a) {
    asm volatile("ldmatrix.sync.aligned.m8n8.x4.trans.shared.b16 {%0,%1,%2,%3}, [%4];"
        : "=r"(r[0]), "=r"(r[1]), "=r"(r[2]), "=r"(r[3]) : "r"(a));
}
__device__ __forceinline__ void mma_f16(float* d, const uint32_t* a, const uint32_t* b) {
    asm volatile("mma.sync.aligned.m16n8k16.row.col.f32.f16.f16.f32 "
        "{%0,%1,%2,%3}, {%4,%5,%6,%7}, {%8,%9}, {%0,%1,%2,%3};"
        : "+f"(d[0]), "+f"(d[1]), "+f"(d[2]), "+f"(d[3])
        : "r"(a[0]), "r"(a[1]), "r"(a[2]), "r"(a[3]), "r"(b[0]), "r"(b[1]));
}
__device__ __forceinline__ uint32_t pack2h(float x, float y) {
    __half2 h = __halves2half2(__float2half(x), __float2half(y));
    return *(uint32_t*)&h;
}

// 128B-row swizzle (8 chunks of 16B), conflict-free for ldmatrix
#define SWO8(row_, chk_) ((uint32_t)((row_) * 128 + (((chk_) ^ ((row_) & 7)) << 4)))

// ---------------- HMMA NT GEMM, 3-term (pre-router path) ----------------
#define KCH  32
#define MATB  (128 * 64)
#define SWO(row_, chk_) ((uint32_t)((row_) * 64 + (((chk_) ^ (((row_) >> 1) & 3)) << 4)))
#define SMEM3 (3 * 4 * MATB)     // 98304

// EPI: 1 fp32+Res; 3 hi/lo
template<int EPI>
__global__ void __launch_bounds__(128, 2) hmma_gemm(
    const __half* __restrict__ Ahi, const __half* __restrict__ Alo,
    const __half* __restrict__ Bhi, const __half* __restrict__ Blo,
    float* __restrict__ C, const float* __restrict__ Res,
    __half* __restrict__ Chi, __half* __restrict__ Clo,
    int N, int K)
{
    constexpr uint32_t STGB = 4 * MATB;
    extern __shared__ char smem[];
    uint32_t sbase = smem_u32(smem);
    int by = blockIdx.y, bx = blockIdx.x;

    int tid = threadIdx.x, wid = tid >> 5, lane = tid & 31;
    int warpM = (wid >> 1) * 64, warpN = (wid & 1) * 64;

    int lrow = tid >> 2;
    int lchk = tid & 3;
    const __half* pAh = Ahi + (size_t)(by * 128 + lrow) * K + lchk * 8;
    const __half* pAl = Alo + (size_t)(by * 128 + lrow) * K + lchk * 8;
    const __half* pB0 = Bhi + (size_t)(bx * 128 + lrow) * K + lchk * 8;
    const __half* pB1 = Blo + (size_t)(bx * 128 + lrow) * K + lchk * 8;
    uint32_t so = SWO(lrow, lchk);

#define LOADST(s_) do { \
        uint32_t sb_ = sbase + ((s_) % 3) * STGB; \
        size_t ko_ = (size_t)(s_) * KCH; \
        _Pragma("unroll") \
        for (int p_ = 0; p_ < 4; p_++) { \
            uint32_t o_ = so + p_ * (32 * 64); \
            size_t g_ = ko_ + (size_t)p_ * 32 * K; \
            cpa16(sb_ + o_,            pAh + g_); \
            cpa16(sb_ + MATB + o_,     pAl + g_); \
            cpa16(sb_ + 2 * MATB + o_, pB0 + g_); \
            cpa16(sb_ + 3 * MATB + o_, pB1 + g_); \
        } \
        cp_commit(); \
    } while (0)

    float acc[4][8][4];
#pragma unroll
    for (int i = 0; i < 4; i++)
#pragma unroll
        for (int j = 0; j < 8; j++)
#pragma unroll
            for (int q = 0; q < 4; q++) acc[i][j][q] = 0.f;

    int S = K / KCH;
    LOADST(0);
    LOADST(1);

    int a_r = lane & 15;
    int a_c = lane >> 4;
    int b_r = ((lane >> 3) & 1) * 8 + (lane & 7);
    int b_c = lane >> 4;

    for (int s = 0; s < S; s++) {
        if (s == S - 1) cp_wait<0>(); else cp_wait<1>();
        __syncthreads();
        if (s + 2 < S) LOADST(s + 2);

        uint32_t sa = sbase + (s % 3) * STGB;
#pragma unroll
        for (int ks = 0; ks < 2; ks++) {
            uint32_t ah[4][4], al[4][4], bhf[8][2];
#pragma unroll
            for (int i = 0; i < 4; i++) {
                int row = warpM + 16 * i + a_r;
                uint32_t ad = sa + SWO(row, ks * 2 + a_c);
                ldm_x4(ah[i], ad);
                ldm_x4(al[i], ad + MATB);
            }
#pragma unroll
            for (int jj = 0; jj < 4; jj++) {
                int row = warpN + 16 * jj + b_r;
                uint32_t bd = sa + 2 * MATB + SWO(row, ks * 2 + b_c);
                uint32_t q[4];
                ldm_x4(q, bd);
                bhf[2 * jj][0] = q[0]; bhf[2 * jj][1] = q[2];
                bhf[2 * jj + 1][0] = q[1]; bhf[2 * jj + 1][1] = q[3];
            }
#pragma unroll
            for (int i = 0; i < 4; i++)
#pragma unroll
                for (int j = 0; j < 8; j++)
                    mma_f16(acc[i][j], ah[i], bhf[j]);
#pragma unroll
            for (int i = 0; i < 4; i++)
#pragma unroll
                for (int j = 0; j < 8; j++)
                    mma_f16(acc[i][j], al[i], bhf[j]);
            uint32_t blf[8][2];
#pragma unroll
            for (int jj = 0; jj < 4; jj++) {
                int row = warpN + 16 * jj + b_r;
                uint32_t bd = sa + 3 * MATB + SWO(row, ks * 2 + b_c);
                uint32_t p[4];
                ldm_x4(p, bd);
                blf[2 * jj][0] = p[0]; blf[2 * jj][1] = p[2];
                blf[2 * jj + 1][0] = p[1]; blf[2 * jj + 1][1] = p[3];
            }
#pragma unroll
            for (int i = 0; i < 4; i++)
#pragma unroll
                for (int j = 0; j < 8; j++)
                    mma_f16(acc[i][j], ah[i], blf[j]);
        }
    }
#undef LOADST

    int r0 = lane >> 2, c0 = (lane & 3) * 2;
#pragma unroll
    for (int i = 0; i < 4; i++) {
#pragma unroll
        for (int j = 0; j < 8; j++) {
            int row = by * 128 + warpM + 16 * i + r0;
            int col = bx * 128 + warpN + 8 * j + c0;
#pragma unroll
            for (int half = 0; half < 2; half++) {
                size_t off = (size_t)(row + half * 8) * N + col;
                float v0 = acc[i][j][2 * half];
                float v1 = acc[i][j][2 * half + 1];
                if (EPI == 1) {
                    float2 rr = *(const float2*)(Res + off);
                    *(float2*)(C + off) = make_float2(v0 + rr.x, v1 + rr.y);
                } else {
                    __half h0 = __float2half(v0);
                    __half h1 = __float2half(v1);
                    __half l0 = __float2half(v0 - __half2float(h0));
                    __half l1 = __float2half(v1 - __half2float(h1));
                    *(__half2*)(Chi + off) = __halves2half2(h0, h1);
                    *(__half2*)(Clo + off) = __halves2half2(l0, l1);
                }
            }
        }
    }
}

// ---------------- MoE GEMM: 2-term, KCH=64, NSTG=2 ----------------
// fc1 (EPI=2): A rows gathered via stok indirection; gelu -> hi/lo out.
// fc2 (EPI=4): A contiguous (hid); epilogue atomicAdd(out + tok*D, w*v).
#define MATB64 16384
#define MG_STGB (3 * MATB64)
#define MG_SMEM (2 * MG_STGB)    // 98304 -> 2 CTAs/SM

template<int EPI>
__global__ void __launch_bounds__(128, 2) moe_gemm(
    const __half* __restrict__ Ahi, const __half* __restrict__ Alo,
    const __half* __restrict__ Bf, size_t bstride,
    const int* __restrict__ tile_e,
    const int* __restrict__ stok, const float* __restrict__ sw,
    __half* __restrict__ Chi, __half* __restrict__ Clo,
    float* __restrict__ Out,
    int N, int K)
{
    extern __shared__ char smem[];
    uint32_t sbase = smem_u32(smem);
    int by = blockIdx.y, bx = blockIdx.x;
    int e = tile_e[by];
    if (e < 0) return;
    const __half* B = Bf + (size_t)e * bstride;

    int tid = threadIdx.x, wid = tid >> 5, lane = tid & 31;
    int warpM = (wid >> 1) * 64, warpN = (wid & 1) * 64;

    // loader: thread tid owns row tid of each matrix (8 chunks of 16B)
    const __half* pAh;
    const __half* pAl;
    if (EPI == 2) {
        int tok = stok[by * 128 + tid];
        if (tok < 0) tok = 0;
        pAh = Ahi + (size_t)tok * K;
        pAl = Alo + (size_t)tok * K;
    } else {
        pAh = Ahi + (size_t)(by * 128 + tid) * K;
        pAl = Alo + (size_t)(by * 128 + tid) * K;
    }
    const __half* pB = B + (size_t)(bx * 128 + tid) * K;

#define MLOAD(s_) do { \
        uint32_t sb_ = sbase + ((s_) & 1) * MG_STGB; \
        int ko_ = (s_) * 64; \
        _Pragma("unroll") \
        for (int c_ = 0; c_ < 8; c_++) { \
            uint32_t o_ = SWO8(tid, c_); \
            cpa16(sb_ + o_,              pAh + ko_ + c_ * 8); \
            cpa16(sb_ + MATB64 + o_,     pAl + ko_ + c_ * 8); \
            cpa16(sb_ + 2 * MATB64 + o_, pB  + ko_ + c_ * 8); \
        } \
        cp_commit(); \
    } while (0)

    float acc[4][8][4];
#pragma unroll
    for (int i = 0; i < 4; i++)
#pragma unroll
        for (int j = 0; j < 8; j++)
#pragma unroll
            for (int q = 0; q < 4; q++) acc[i][j][q] = 0.f;

    int S = K / 64;
    MLOAD(0);

    int a_r = lane & 15;
    int a_c = lane >> 4;
    int b_r = ((lane >> 3) & 1) * 8 + (lane & 7);
    int b_c = lane >> 4;

    for (int s = 0; s < S; s++) {
        cp_wait<0>();          // stage s landed (issued at s-1, covered by compute s-1)
        __syncthreads();       // buffer (s+1)&1 free (read finished at compute s-1)
        if (s + 1 < S) MLOAD(s + 1);

        uint32_t sa = sbase + (s & 1) * MG_STGB;
#pragma unroll
        for (int ks = 0; ks < 4; ks++) {
            uint32_t ah[4][4], al[4][4], bf2[8][2];
#pragma unroll
            for (int i = 0; i < 4; i++) {
                uint32_t ad = sa + SWO8(warpM + 16 * i + a_r, ks * 2 + a_c);
                ldm_x4(ah[i], ad);
                ldm_x4(al[i], ad + MATB64);
            }
#pragma unroll
            for (int jj = 0; jj < 4; jj++) {
                uint32_t bd = sa + 2 * MATB64 + SWO8(warpN + 16 * jj + b_r, ks * 2 + b_c);
                uint32_t q[4];
                ldm_x4(q, bd);
                bf2[2 * jj][0] = q[0]; bf2[2 * jj][1] = q[2];
                bf2[2 * jj + 1][0] = q[1]; bf2[2 * jj + 1][1] = q[3];
            }
#pragma unroll
            for (int i = 0; i < 4; i++)
#pragma unroll
                for (int j = 0; j < 8; j++)
                    mma_f16(acc[i][j], ah[i], bf2[j]);
#pragma unroll
            for (int i = 0; i < 4; i++)
#pragma unroll
                for (int j = 0; j < 8; j++)
                    mma_f16(acc[i][j], al[i], bf2[j]);
        }
    }
#undef MLOAD

    int r0 = lane >> 2, c0 = (lane & 3) * 2;
    if (EPI == 2) {
#pragma unroll
        for (int i = 0; i < 4; i++) {
#pragma unroll
            for (int j = 0; j < 8; j++) {
                int row = by * 128 + warpM + 16 * i + r0;
                int col = bx * 128 + warpN + 8 * j + c0;
#pragma unroll
                for (int half = 0; half < 2; half++) {
                    size_t off = (size_t)(row + half * 8) * N + col;
                    float v0 = gelu_f(acc[i][j][2 * half]);
                    float v1 = gelu_f(acc[i][j][2 * half + 1]);
                    __half h0 = __float2half(v0);
                    __half h1 = __float2half(v1);
                    __half l0 = __float2half(v0 - __half2float(h0));
                    __half l1 = __float2half(v1 - __half2float(h1));
                    *(__half2*)(Chi + off) = __halves2half2(h0, h1);
                    *(__half2*)(Clo + off) = __halves2half2(l0, l1);
                }
            }
        }
    } else {
        // fc2: scatter-accumulate into out with combine weights
#pragma unroll
        for (int i = 0; i < 4; i++) {
#pragma unroll
            for (int half = 0; half < 2; half++) {
                int row = by * 128 + warpM + 16 * i + r0 + half * 8;
                int tok = stok[row];
                if (tok < 0) continue;
                float wt = sw[row];
                float* obase = Out + (size_t)tok * DMODEL;
#pragma unroll
                for (int j = 0; j < 8; j++) {
                    int col = bx * 128 + warpN + 8 * j + c0;
                    atomicAdd(obase + col,     wt * acc[i][j][2 * half]);
                    atomicAdd(obase + col + 1, wt * acc[i][j][2 * half + 1]);
                }
            }
        }
    }
}

// ---------------- HMMA flash attention, double-buffered K/V ----------------
#define AT_Q    0
#define AT_QL   8192
#define AT_KV   16384
#define AT_SLOT 32768
#define AT_SMEM (16384 + 2 * 32768)

__global__ void __launch_bounds__(128) attn_hmma(
    const __half* __restrict__ qkvHi, const __half* __restrict__ qkvLo,
    __half* __restrict__ oHi, __half* __restrict__ oLo)
{
    extern __shared__ char smem[];
    uint32_t sbase = smem_u32(smem);
    int qi = blockIdx.x;
    int bh = blockIdx.y;
    int b = bh >> 4, h = bh & 15;
    int tid = threadIdx.x, wid = tid >> 5, lane = tid & 31;
    int warpM = wid * 16;

    const size_t tokbase = (size_t)b * TSEQ * 3072;
    const __half* qH = qkvHi + tokbase + h * 64;
    const __half* qL = qkvLo + tokbase + h * 64;
    const __half* kH = qH + 1024;
    const __half* kL = qL + 1024;
    const __half* vH = qH + 2048;
    const __half* vL = qL + 2048;

    int lrow = tid >> 1;
    int lc0 = (tid & 1) * 4;

#pragma unroll
    for (int i = 0; i < 4; i++) {
        int chk = lc0 + i;
        size_t g = (size_t)(qi * 64 + lrow) * 3072 + chk * 8;
        cpa16(sbase + AT_Q + SWO8(lrow, chk), qH + g);
        cpa16(sbase + AT_QL + SWO8(lrow, chk), qL + g);
    }
    cp_commit();

#define LOADKV(jt_) do { \
        uint32_t slot_ = sbase + AT_KV + ((jt_) & 1) * AT_SLOT; \
        _Pragma("unroll") \
        for (int i_ = 0; i_ < 4; i_++) { \
            int chk_ = lc0 + i_; \
            size_t g_ = (size_t)((jt_) * 64 + lrow) * 3072 + chk_ * 8; \
            uint32_t soff_ = SWO8(lrow, chk_); \
            cpa16(slot_ + soff_,         kH + g_); \
            cpa16(slot_ + 8192 + soff_,  kL + g_); \
            cpa16(slot_ + 16384 + soff_, vH + g_); \
            cpa16(slot_ + 24576 + soff_, vL + g_); \
        } \
        cp_commit(); \
    } while (0)

    LOADKV(0);

    float acc_o[8][4];
#pragma unroll
    for (int j = 0; j < 8; j++)
#pragma unroll
        for (int q = 0; q < 4; q++) acc_o[j][q] = 0.f;
    float mrow[2] = {-1e30f, -1e30f};
    float lrw[2] = {0.f, 0.f};

    int a_r = lane & 15;
    int a_c = lane >> 4;
    int b_r = ((lane >> 3) & 1) * 8 + (lane & 7);
    int b_c = lane >> 4;

    for (int jt = 0; jt <= qi; jt++) {
        __syncthreads();
        if (jt + 1 <= qi) { LOADKV(jt + 1); cp_wait<1>(); }
        else cp_wait<0>();
        __syncthreads();

        uint32_t slot = sbase + AT_KV + (jt & 1) * AT_SLOT;

        float s[8][4];
#pragma unroll
        for (int j = 0; j < 8; j++)
#pragma unroll
            for (int q = 0; q < 4; q++) s[j][q] = 0.f;

#pragma unroll
        for (int kc = 0; kc < 4; kc++) {
            uint32_t ah[4], al[4], kf[8][2];
            uint32_t ad = sbase + AT_Q + SWO8(warpM + a_r, kc * 2 + a_c);
            ldm_x4(ah, ad);
            ldm_x4(al, ad + (AT_QL - AT_Q));
#pragma unroll
            for (int jj = 0; jj < 4; jj++) {
                uint32_t bd = slot + SWO8(16 * jj + b_r, kc * 2 + b_c);
                uint32_t q[4];
                ldm_x4(q, bd);
                kf[2 * jj][0] = q[0]; kf[2 * jj][1] = q[2];
                kf[2 * jj + 1][0] = q[1]; kf[2 * jj + 1][1] = q[3];
            }
#pragma unroll
            for (int j = 0; j < 8; j++)
                mma_f16(s[j], ah, kf[j]);
#pragma unroll
            for (int j = 0; j < 8; j++)
                mma_f16(s[j], al, kf[j]);
            uint32_t klf[8][2];
#pragma unroll
            for (int jj = 0; jj < 4; jj++) {
                uint32_t bd = slot + 8192 + SWO8(16 * jj + b_r, kc * 2 + b_c);
                uint32_t p[4];
                ldm_x4(p, bd);
                klf[2 * jj][0] = p[0]; klf[2 * jj][1] = p[2];
                klf[2 * jj + 1][0] = p[1]; klf[2 * jj + 1][1] = p[3];
            }
#pragma unroll
            for (int j = 0; j < 8; j++)
                mma_f16(s[j], ah, klf[j]);
        }

        int rA = qi * 64 + warpM + (lane >> 2);
        int cbase = jt * 64 + (lane & 3) * 2;
#pragma unroll
        for (int j = 0; j < 8; j++) {
#pragma unroll
            for (int q = 0; q < 4; q++) {
                float v = s[j][q] * 0.125f;
                if (jt == qi) {
                    int col = cbase + j * 8 + (q & 1);
                    int row = rA + (q >= 2 ? 8 : 0);
                    if (col > row) v = -1e30f;
                }
                s[j][q] = v;
            }
        }

#pragma unroll
        for (int hf = 0; hf < 2; hf++) {
            float mt = -1e30f;
#pragma unroll
            for (int j = 0; j < 8; j++)
                mt = fmaxf(mt, fmaxf(s[j][2 * hf], s[j][2 * hf + 1]));
            mt = fmaxf(mt, __shfl_xor_sync(0xffffffffu, mt, 1));
            mt = fmaxf(mt, __shfl_xor_sync(0xffffffffu, mt, 2));
            float mn = fmaxf(mrow[hf], mt);
            float alpha = __expf(mrow[hf] - mn);
            float ls = 0.f;
#pragma unroll
            for (int j = 0; j < 8; j++) {
                float p0 = __expf(s[j][2 * hf] - mn);
                float p1 = __expf(s[j][2 * hf + 1] - mn);
                s[j][2 * hf] = p0; s[j][2 * hf + 1] = p1;
                ls += p0 + p1;
            }
            ls += __shfl_xor_sync(0xffffffffu, ls, 1);
            ls += __shfl_xor_sync(0xffffffffu, ls, 2);
            lrw[hf] = lrw[hf] * alpha + ls;
            mrow[hf] = mn;
#pragma unroll
            for (int j = 0; j < 8; j++) {
                acc_o[j][2 * hf] *= alpha;
                acc_o[j][2 * hf + 1] *= alpha;
            }
        }

#pragma unroll
        for (int kc = 0; kc < 4; kc++) {
            uint32_t phi[4], plo[4];
            {
                float p00 = s[2 * kc][0], p01 = s[2 * kc][1];
                float p02 = s[2 * kc][2], p03 = s[2 * kc][3];
                float p10 = s[2 * kc + 1][0], p11 = s[2 * kc + 1][1];
                float p12 = s[2 * kc + 1][2], p13 = s[2 * kc + 1][3];
                phi[0] = pack2h(p00, p01);
                phi[1] = pack2h(p02, p03);
                phi[2] = pack2h(p10, p11);
                phi[3] = pack2h(p12, p13);
                __half2 h0 = *(__half2*)&phi[0];
                __half2 h1 = *(__half2*)&phi[1];
                __half2 h2 = *(__half2*)&phi[2];
                __half2 h3 = *(__half2*)&phi[3];
                plo[0] = pack2h(p00 - __half2float(__low2half(h0)), p01 - __half2float(__high2half(h0)));
                plo[1] = pack2h(p02 - __half2float(__low2half(h1)), p03 - __half2float(__high2half(h1)));
                plo[2] = pack2h(p10 - __half2float(__low2half(h2)), p11 - __half2float(__high2half(h2)));
                plo[3] = pack2h(p12 - __half2float(__low2half(h3)), p13 - __half2float(__high2half(h3)));
            }
            uint32_t vfh[8][2], vfl[8][2];
#pragma unroll
            for (int g = 0; g < 4; g++) {
                uint32_t bd = slot + 16384 + SWO8(kc * 16 + b_r, 2 * g + b_c);
                uint32_t q[4];
                ldm_x4t(q, bd);
                vfh[2 * g][0] = q[0]; vfh[2 * g][1] = q[1];
                vfh[2 * g + 1][0] = q[2]; vfh[2 * g + 1][1] = q[3];
                uint32_t p[4];
                ldm_x4t(p, bd + 8192);
                vfl[2 * g][0] = p[0]; vfl[2 * g][1] = p[1];
                vfl[2 * g + 1][0] = p[2]; vfl[2 * g + 1][1] = p[3];
            }
#pragma unroll
            for (int j = 0; j < 8; j++)
                mma_f16(acc_o[j], phi, vfh[j]);
#pragma unroll
            for (int j = 0; j < 8; j++)
                mma_f16(acc_o[j], phi, vfl[j]);
#pragma unroll
            for (int j = 0; j < 8; j++)
                mma_f16(acc_o[j], plo, vfh[j]);
        }
    }
#undef LOADKV

    float inv0 = 1.0f / lrw[0];
    float inv1 = 1.0f / lrw[1];
#pragma unroll
    for (int j = 0; j < 8; j++) {
#pragma unroll
        for (int hf = 0; hf < 2; hf++) {
            int row = b * TSEQ + qi * 64 + warpM + (lane >> 2) + hf * 8;
            int col = h * 64 + j * 8 + (lane & 3) * 2;
            float inv = hf ? inv1 : inv0;
            float v0 = acc_o[j][2 * hf] * inv;
            float v1 = acc_o[j][2 * hf + 1] * inv;
            __half h0 = __float2half(v0);
            __half h1 = __float2half(v1);
            __half l0 = __float2half(v0 - __half2float(h0));
            __half l1 = __float2half(v1 - __half2float(h1));
            size_t off = (size_t)row * DMODEL + col;
            *(__half2*)(oHi + off) = __halves2half2(h0, h1);
            *(__half2*)(oLo + off) = __halves2half2(l0, l1);
        }
    }
}

// ---------------- fp32 -> fp16 hi/lo split ----------------
__global__ __launch_bounds__(256) void split2_kernel(const float* __restrict__ x,
                                                     __half* __restrict__ hi,
                                                     __half* __restrict__ lo, int n4) {
    int i = blockIdx.x * 256 + threadIdx.x;
    if (i >= n4) return;
    float4 v = ((const float4*)x)[i];
    __half h0 = __float2half(v.x), h1 = __float2half(v.y);
    __half h2 = __float2half(v.z), h3 = __float2half(v.w);
    __half l0 = __float2half(v.x - __half2float(h0));
    __half l1 = __float2half(v.y - __half2float(h1));
    __half l2 = __float2half(v.z - __half2float(h2));
    __half l3 = __float2half(v.w - __half2float(h3));
    ((__half2*)hi)[2 * i]     = __halves2half2(h0, h1);
    ((__half2*)hi)[2 * i + 1] = __halves2half2(h2, h3);
    ((__half2*)lo)[2 * i]     = __halves2half2(l0, l1);
    ((__half2*)lo)[2 * i + 1] = __halves2half2(l2, l3);
}

// ---------------- fp32 -> fp16 single (post-router weights) ----------------
__global__ __launch_bounds__(256) void cvt_kernel(const float* __restrict__ x,
                                                  __half* __restrict__ y, int n4) {
    int i = blockIdx.x * 256 + threadIdx.x;
    if (i >= n4) return;
    float4 v = ((const float4*)x)[i];
    ((__half2*)y)[2 * i]     = __floats2half2_rn(v.x, v.y);
    ((__half2*)y)[2 * i + 1] = __floats2half2_rn(v.z, v.w);
}

// ---------------- LayerNorm fused with hi/lo split ----------------
// MODE 0: ln1 (+c), hi/lo only. MODE 1: ln2, fp32 out + hi/lo.
template<int MODE>
__global__ __launch_bounds__(256) void ln_fused(const float* __restrict__ x,
                                                const float* __restrict__ w,
                                                const float* __restrict__ c,
                                                float* __restrict__ outf,
                                                __half* __restrict__ hi,
                                                __half* __restrict__ lo) {
    int row = blockIdx.x;
    int tid = threadIdx.x;
    const float* xr = x + (size_t)row * DMODEL;
    float4 v = *(const float4*)(xr + tid * 4);

    __shared__ float red[8];
    __shared__ float tot;

    float s = v.x + v.y + v.z + v.w;
#pragma unroll
    for (int m = 16; m > 0; m >>= 1) s += __shfl_xor_sync(0xffffffffu, s, m);
    if ((tid & 31) == 0) red[tid >> 5] = s;
    __syncthreads();
    if (tid == 0) { float t = 0.f; for (int i = 0; i < 8; i++) t += red[i]; tot = t; }
    __syncthreads();
    float mean = tot * (1.0f / DMODEL);
    float dx = v.x - mean, dy = v.y - mean, dz = v.z - mean, dw = v.w - mean;
    float s2 = dx * dx + dy * dy + dz * dz + dw * dw;
    __syncthreads();
#pragma unroll
    for (int m = 16; m > 0; m >>= 1) s2 += __shfl_xor_sync(0xffffffffu, s2, m);
    if ((tid & 31) == 0) red[tid >> 5] = s2;
    __syncthreads();
    if (tid == 0) { float t = 0.f; for (int i = 0; i < 8; i++) t += red[i]; tot = t; }
    __syncthreads();
    float inv = rsqrtf(tot * (1.0f / DMODEL) + 1e-5f);

    int d0 = tid * 4;
    float4 w4 = *(const float4*)(w + d0);
    float r0 = dx * inv * w4.x;
    float r1 = dy * inv * w4.y;
    float r2 = dz * inv * w4.z;
    float r3 = dw * inv * w4.w;
    if (MODE == 0) {
        int b = row >> 10;
        float4 c4 = *(const float4*)(c + (size_t)b * DMODEL + d0);
        r0 += c4.x; r1 += c4.y; r2 += c4.z; r3 += c4.w;
    }
    if (MODE == 1)
        *(float4*)(outf + (size_t)row * DMODEL + d0) = make_float4(r0, r1, r2, r3);
    __half h0 = __float2half(r0), h1 = __float2half(r1);
    __half h2 = __float2half(r2), h3 = __float2half(r3);
    __half l0 = __float2half(r0 - __half2float(h0));
    __half l1 = __float2half(r1 - __half2float(h1));
    __half l2 = __float2half(r2 - __half2float(h2));
    __half l3 = __float2half(r3 - __half2float(h3));
    size_t ho = (size_t)row * DMODEL + d0;
    *(__half2*)(hi + ho)     = __halves2half2(h0, h1);
    *(__half2*)(hi + ho + 2) = __halves2half2(h2, h3);
    *(__half2*)(lo + ho)     = __halves2half2(l0, l1);
    *(__half2*)(lo + ho + 2) = __halves2half2(l2, l3);
}

// ---------------- router ----------------
__global__ __launch_bounds__(256) void router_kernel(const float* __restrict__ xn,
                                                     const float* __restrict__ rw,
                                                     int* __restrict__ eidx,
                                                     float* __restrict__ wts) {
    int t = blockIdx.x;
    int tid = threadIdx.x, lane = tid & 31, wp = tid >> 5;
    const float* xr = xn + (size_t)t * DMODEL;
    const float* wr = rw + (size_t)wp * DMODEL;
    float s = 0.f;
    for (int d = lane * 4; d < DMODEL; d += 128) {
        float4 a = *(const float4*)(xr + d);
        float4 b = *(const float4*)(wr + d);
        s += a.x * b.x + a.y * b.y + a.z * b.z + a.w * b.w;
    }
#pragma unroll
    for (int mm = 16; mm > 0; mm >>= 1) s += __shfl_xor_sync(0xffffffffu, s, mm);
    __shared__ float lg[8];
    if (lane == 0) lg[wp] = s;
    __syncthreads();
    if (tid == 0) {
        float mx = lg[0];
        for (int e = 1; e < NE; e++) mx = fmaxf(mx, lg[e]);
        float p[NE]; float sum = 0.f;
        for (int e = 0; e < NE; e++) { p[e] = expf(lg[e] - mx); sum += p[e]; }
        float inv = 1.0f / sum;
        for (int e = 0; e < NE; e++) {
            float v = p[e] * inv + 1e-9f;
            p[e] = fminf(fmaxf(v, 1e-9f), 1.0f - 1e-9f);
        }
        int i0 = 0;
        for (int e = 1; e < NE; e++) if (p[e] > p[i0]) i0 = e;
        int i1 = (i0 == 0) ? 1 : 0;
        for (int e = 0; e < NE; e++) if (e != i0 && p[e] > p[i1]) i1 = e;
        float d2 = 1.0f / (p[i0] + p[i1]);
        eidx[2 * t] = i0; eidx[2 * t + 1] = i1;
        wts[2 * t] = p[i0] * d2; wts[2 * t + 1] = p[i1] * d2;
    }
}

// ---------------- build slot tables ----------------
__global__ __launch_bounds__(256) void build_kernel(const int* __restrict__ eidx,
                                                    const float* __restrict__ wts,
                                                    int* __restrict__ stok,
                                                    float* __restrict__ sw,
                                                    int* __restrict__ tile_e) {
    __shared__ int cnt[NE];
    __shared__ int off[NE];
    int tid = threadIdx.x;
    if (tid < NE) cnt[tid] = 0;
    __syncthreads();
    for (int a = tid; a < BT * 2; a += 256) atomicAdd(&cnt[eidx[a]], 1);
    __syncthreads();
    if (tid == 0) {
        int o = 0;
        for (int e = 0; e < NE; e++) { off[e] = o; o = (o + cnt[e] + 127) & ~127; }
        for (int tt = 0; tt < NTILES; tt++) tile_e[tt] = -1;
        for (int e = 0; e < NE; e++) {
            int nt = (cnt[e] + 127) >> 7;
            int t0 = off[e] >> 7;
            for (int i = 0; i < nt; i++) tile_e[t0 + i] = e;
        }
    }
    __syncthreads();
    if (tid < NE) cnt[tid] = 0;
    for (int r = tid; r < CAP; r += 256) stok[r] = -1;
    __syncthreads();
    for (int a = tid; a < BT * 2; a += 256) {
        int e = eidx[a];
        int pos = atomicAdd(&cnt[e], 1);
        int r = off[e] + pos;
        stok[r] = a >> 1;
        sw[r] = wts[a];
    }
}

// ---------------- host launcher ----------------
extern "C" void kernel_launch(void* const* d_in, const int* in_sizes, int n_in,
                              void* d_out, int out_size) {
    const float* x        = (const float*)d_in[0];
    const float* c        = (const float*)d_in[1];
    const float* ln1_w    = (const float*)d_in[2];
    const float* w_qkv    = (const float*)d_in[3];
    const float* w_proj   = (const float*)d_in[4];
    const float* ln2_w    = (const float*)d_in[5];
    const float* router_w = (const float*)d_in[6];
    const float* ew1      = (const float*)d_in[7];
    const float* ew2      = (const float*)d_in[8];
    float* out = (float*)d_out;

    float *p_x2, *p_wts, *p_sw;
    int *p_eidx, *p_stok, *p_te;
    __half *p_aHi, *p_aLo, *p_qkvHi, *p_qkvLo, *p_wHi, *p_wLo, *p_hidHi, *p_hidLo;
    cudaGetSymbolAddress((void**)&p_x2,    g_x2);
    cudaGetSymbolAddress((void**)&p_wts,   g_wts);
    cudaGetSymbolAddress((void**)&p_sw,    g_sw);
    cudaGetSymbolAddress((void**)&p_eidx,  g_eidx);
    cudaGetSymbolAddress((void**)&p_stok,  g_stok);
    cudaGetSymbolAddress((void**)&p_te,    g_tile_e);
    cudaGetSymbolAddress((void**)&p_aHi,   g_aHi);
    cudaGetSymbolAddress((void**)&p_aLo,   g_aLo);
    cudaGetSymbolAddress((void**)&p_qkvHi, g_qkvHi);
    cudaGetSymbolAddress((void**)&p_qkvLo, g_qkvLo);
    cudaGetSymbolAddress((void**)&p_wHi,   g_wHi);
    cudaGetSymbolAddress((void**)&p_wLo,   g_wLo);
    cudaGetSymbolAddress((void**)&p_hidHi, g_hidHi);
    cudaGetSymbolAddress((void**)&p_hidLo, g_hidLo);

    cudaFuncSetAttribute((const void*)hmma_gemm<1>, cudaFuncAttributeMaxDynamicSharedMemorySize, SMEM3);
    cudaFuncSetAttribute((const void*)hmma_gemm<3>, cudaFuncAttributeMaxDynamicSharedMemorySize, SMEM3);
    cudaFuncSetAttribute((const void*)moe_gemm<2>, cudaFuncAttributeMaxDynamicSharedMemorySize, MG_SMEM);
    cudaFuncSetAttribute((const void*)moe_gemm<4>, cudaFuncAttributeMaxDynamicSharedMemorySize, MG_SMEM);
    cudaFuncSetAttribute(attn_hmma, cudaFuncAttributeMaxDynamicSharedMemorySize, AT_SMEM);

    // 1) h = LN1(x)*w + c -> fp16 hi/lo
    ln_fused<0><<<BT, 256>>>(x, ln1_w, c, nullptr, p_aHi, p_aLo);
    split2_kernel<<<(3 * DMODEL * DMODEL / 4 + 255) / 256, 256>>>(w_qkv, p_wHi, p_wLo, 3 * DMODEL * DMODEL / 4);

    // 2) qkv = h @ w_qkv^T -> fp16 hi/lo (3-term)
    hmma_gemm<3><<<dim3(24, 32), 128, SMEM3>>>(p_aHi, p_aLo, p_wHi, p_wLo,
                                               nullptr, nullptr, p_qkvHi, p_qkvLo, 3072, 1024);

    // 3) causal attention
    attn_hmma<<<dim3(16, 64), 128, AT_SMEM>>>(p_qkvHi, p_qkvLo, p_aHi, p_aLo);

    // 4) x2 = x + o @ w_proj^T (3-term)
    split2_kernel<<<(DMODEL * DMODEL / 4 + 255) / 256, 256>>>(w_proj, p_wHi, p_wLo, DMODEL * DMODEL / 4);
    hmma_gemm<1><<<dim3(8, 32), 128, SMEM3>>>(p_aHi, p_aLo, p_wHi, p_wLo,
                                              p_x2, x, nullptr, nullptr, 1024, 1024);

    // 5) xn = LN2(x2) -> out (fp32 base for combine) + fp16 hi/lo
    ln_fused<1><<<BT, 256>>>(p_x2, ln2_w, nullptr, out, p_aHi, p_aLo);

    // 6) router + slot tables (fp32 routing, exact)
    router_kernel<<<BT, 256>>>(out, router_w, p_eidx, p_wts);
    build_kernel<<<1, 256>>>(p_eidx, p_wts, p_stok, p_sw, p_te);

    // 7) fc1: hid = gelu(gather(xn) @ w1[e]^T), A gathered in-kernel
    cvt_kernel<<<(NE * FF * DMODEL / 4 + 255) / 256, 256>>>(ew1, p_wHi, NE * FF * DMODEL / 4);
    moe_gemm<2><<<dim3(32, NTILES), 128, MG_SMEM>>>(p_aHi, p_aLo, p_wHi, (size_t)FF * DMODEL,
                                                    p_te, p_stok, nullptr,
                                                    p_hidHi, p_hidLo, nullptr, FF, 1024);

    // 8) fc2: out += w_k * (hid @ w2[e]^T), scatter-accumulate in epilogue
    cvt_kernel<<<(NE * DMODEL * FF / 4 + 255) / 256, 256>>>(ew2, p_wHi, NE * DMODEL * FF / 4);
    moe_gemm<4><<<dim3(8, NTILES), 128, MG_SMEM>>>(p_hidHi, p_hidLo, p_wHi, (size_t)DMODEL * FF,
                                                   p_te, p_stok, p_sw,
                                                   nullptr, nullptr, out, 1024, 4096);
}

// round 13
// speedup vs baseline: 1.3822x; 1.3822x over previous
#include <cuda_runtime.h>
#include <cuda_fp16.h>
#include <math.h>
#include <stdint.h>

// Problem dims
#define BATCH 4
#define TSEQ  1024
#define BT    4096
#define DMODEL 1024
#define NE    8
#define FF    4096
#define CAP   9216
#define NTILES 72

// ---------------- static device scratch ----------------
__device__ float g_x2 [BT * DMODEL];
__device__ float g_xn [BT * DMODEL];
__device__ float g_eo [CAP * DMODEL];
__device__ int   g_eidx[BT * 2];
__device__ float g_wts [BT * 2];
__device__ int   g_rows[BT * 2];
__device__ int   g_stok[CAP];          // slot -> token (-1 = padding)
__device__ int   g_tile_e[NTILES];

// fp16 split scratch
__device__ __half g_aHi [BT * DMODEL];
__device__ __half g_aLo [BT * DMODEL];
__device__ __half g_qkvHi[BT * 3 * DMODEL];
__device__ __half g_qkvLo[BT * 3 * DMODEL];
__device__ __half g_wHi [NE * FF * DMODEL];
__device__ __half g_wLo [NE * FF * DMODEL];
__device__ __half g_hidHi[CAP * FF];
__device__ __half g_hidLo[CAP * FF];

__device__ __forceinline__ float gelu_f(float v) {
    return 0.5f * v * (1.0f + erff(v * 0.70710678118654752f));
}

// ---------------- PTX helpers ----------------
__device__ __forceinline__ uint32_t smem_u32(const void* p) {
    uint32_t a;
    asm("{ .reg .u64 t; cvta.to.shared.u64 t, %1; cvt.u32.u64 %0, t; }" : "=r"(a) : "l"(p));
    return a;
}
__device__ __forceinline__ void cpa16(uint32_t dst, const void* src) {
    asm volatile("cp.async.cg.shared.global [%0], [%1], 16;" :: "r"(dst), "l"(src));
}
__device__ __forceinline__ void cp_commit() { asm volatile("cp.async.commit_group;" ::: "memory"); }
template<int NPEND> __device__ __forceinline__ void cp_wait() {
    asm volatile("cp.async.wait_group %0;" :: "n"(NPEND) : "memory");
}
__device__ __forceinline__ void ldm_x4(uint32_t* r, uint32_t a) {
    asm volatile("ldmatrix.sync.aligned.m8n8.x4.shared.b16 {%0,%1,%2,%3}, [%4];"
        : "=r"(r[0]), "=r"(r[1]), "=r"(r[2]), "=r"(r[3]) : "r"(a));
}
__device__ __forceinline__ void ldm_x4t(uint32_t* r, uint32_t a) {
    asm volatile("ldmatrix.sync.aligned.m8n8.x4.trans.shared.b16 {%0,%1,%2,%3}, [%4];"
        : "=r"(r[0]), "=r"(r[1]), "=r"(r[2]), "=r"(r[3]) : "r"(a));
}
__device__ __forceinline__ void mma_f16(float* d, const uint32_t* a, const uint32_t* b) {
    asm volatile("mma.sync.aligned.m16n8k16.row.col.f32.f16.f16.f32 "
        "{%0,%1,%2,%3}, {%4,%5,%6,%7}, {%8,%9}, {%0,%1,%2,%3};"
        : "+f"(d[0]), "+f"(d[1]), "+f"(d[2]), "+f"(d[3])
        : "r"(a[0]), "r"(a[1]), "r"(a[2]), "r"(a[3]), "r"(b[0]), "r"(b[1]));
}
__device__ __forceinline__ uint32_t pack2h(float x, float y) {
    __half2 h = __halves2half2(__float2half(x), __float2half(y));
    return *(uint32_t*)&h;
}

// ---------------- HMMA NT GEMM ----------------
// TERMS=3: D = Ahi*Bhi + Ahi*Blo + Alo*Bhi  (NSTG=3, 4 mats/stage)
// TERMS=2: D = (Ahi+Alo)*B                  (NSTG=4, 3 mats/stage)
// GATHER=1: A row g is aHi/aLo[stok[g]] (fc1 in-kernel gather)
#define KCH  32
#define MATB  (128 * 64)
#define SWO(row_, chk_) ((uint32_t)((row_) * 64 + (((chk_) ^ (((row_) >> 1) & 3)) << 4)))

// EPI: 0 fp32; 1 fp32+Res; 2 gelu->hi/lo; 3 hi/lo
template<int EPI, int TERMS, int GATHER>
__global__ void __launch_bounds__(128, 2) hmma_gemm(
    const __half* __restrict__ Ahi, const __half* __restrict__ Alo,
    const __half* __restrict__ Bhi, const __half* __restrict__ Blo,
    size_t bstride, const int* __restrict__ tile_e,
    const int* __restrict__ stok,
    float* __restrict__ C, const float* __restrict__ Res,
    __half* __restrict__ Chi, __half* __restrict__ Clo,
    int N, int K)
{
    constexpr int NMAT = (TERMS == 3) ? 4 : 3;
    constexpr int NSTG_T = (TERMS == 3) ? 3 : 4;
    constexpr uint32_t STGB = NMAT * MATB;
    extern __shared__ char smem[];
    uint32_t sbase = smem_u32(smem);
    int by = blockIdx.y, bx = blockIdx.x;

    const __half* Bh = Bhi;
    const __half* Bl = Blo;
    if (tile_e) {
        int e = tile_e[by];
        if (e < 0) return;
        Bh += (size_t)e * bstride;
        if (TERMS == 3) Bl += (size_t)e * bstride;
    }

    int tid = threadIdx.x, wid = tid >> 5, lane = tid & 31;
    int warpM = (wid >> 1) * 64, warpN = (wid & 1) * 64;

    int lrow = tid >> 2;
    int lchk = tid & 3;
    const __half* pAh = Ahi + (size_t)(by * 128 + lrow) * K + lchk * 8;
    const __half* pAl = Alo + (size_t)(by * 128 + lrow) * K + lchk * 8;
    const __half* pAhp[4];
    const __half* pAlp[4];
    if (GATHER) {
#pragma unroll
        for (int p = 0; p < 4; p++) {
            int slot = by * 128 + lrow + p * 32;
            int tok = stok[slot];
            if (tok < 0) tok = 0;
            pAhp[p] = Ahi + (size_t)tok * K + lchk * 8;
            pAlp[p] = Alo + (size_t)tok * K + lchk * 8;
        }
    }
    const __half* pB0 = Bh + (size_t)(bx * 128 + lrow) * K + lchk * 8;
    const __half* pB1 = (TERMS == 3) ? (Bl + (size_t)(bx * 128 + lrow) * K + lchk * 8) : nullptr;
    uint32_t so = SWO(lrow, lchk);

#define LOADST(s_) do { \
        uint32_t sb_ = sbase + ((s_) % NSTG_T) * STGB; \
        size_t ko_ = (size_t)(s_) * KCH; \
        _Pragma("unroll") \
        for (int p_ = 0; p_ < 4; p_++) { \
            uint32_t o_ = so + p_ * (32 * 64); \
            size_t g_ = ko_ + (size_t)p_ * 32 * K; \
            const __half* ah_ = GATHER ? (pAhp[p_] + ko_) : (pAh + g_); \
            const __half* al_ = GATHER ? (pAlp[p_] + ko_) : (pAl + g_); \
            cpa16(sb_ + o_,            ah_); \
            cpa16(sb_ + MATB + o_,     al_); \
            cpa16(sb_ + 2 * MATB + o_, pB0 + g_); \
            if (TERMS == 3) cpa16(sb_ + 3 * MATB + o_, pB1 + g_); \
        } \
        cp_commit(); \
    } while (0)

    float acc[4][8][4];
#pragma unroll
    for (int i = 0; i < 4; i++)
#pragma unroll
        for (int j = 0; j < 8; j++)
#pragma unroll
            for (int q = 0; q < 4; q++) acc[i][j][q] = 0.f;

    int S = K / KCH;
    LOADST(0);
    LOADST(1);
    if (NSTG_T == 4) LOADST(2);

    int a_r = lane & 15;
    int a_c = lane >> 4;
    int b_r = ((lane >> 3) & 1) * 8 + (lane & 7);
    int b_c = lane >> 4;

    for (int s = 0; s < S; s++) {
        if (NSTG_T == 4) {
            if (s + 2 <= S - 1) cp_wait<2>();
            else if (s + 1 <= S - 1) cp_wait<1>();
            else cp_wait<0>();
        } else {
            if (s + 1 <= S - 1) cp_wait<1>();
            else cp_wait<0>();
        }
        __syncthreads();
        if (s + NSTG_T - 1 < S) LOADST(s + NSTG_T - 1);

        uint32_t sa = sbase + (s % NSTG_T) * STGB;
#pragma unroll
        for (int ks = 0; ks < 2; ks++) {
            uint32_t ah[4][4], al[4][4], bhf[8][2];
#pragma unroll
            for (int i = 0; i < 4; i++) {
                int row = warpM + 16 * i + a_r;
                uint32_t ad = sa + SWO(row, ks * 2 + a_c);
                ldm_x4(ah[i], ad);
                ldm_x4(al[i], ad + MATB);
            }
#pragma unroll
            for (int jj = 0; jj < 4; jj++) {
                int row = warpN + 16 * jj + b_r;
                uint32_t bd = sa + 2 * MATB + SWO(row, ks * 2 + b_c);
                uint32_t q[4];
                ldm_x4(q, bd);
                bhf[2 * jj][0] = q[0]; bhf[2 * jj][1] = q[2];
                bhf[2 * jj + 1][0] = q[1]; bhf[2 * jj + 1][1] = q[3];
            }
#pragma unroll
            for (int i = 0; i < 4; i++)
#pragma unroll
                for (int j = 0; j < 8; j++)
                    mma_f16(acc[i][j], ah[i], bhf[j]);
#pragma unroll
            for (int i = 0; i < 4; i++)
#pragma unroll
                for (int j = 0; j < 8; j++)
                    mma_f16(acc[i][j], al[i], bhf[j]);
            if (TERMS == 3) {
                uint32_t blf[8][2];
#pragma unroll
                for (int jj = 0; jj < 4; jj++) {
                    int row = warpN + 16 * jj + b_r;
                    uint32_t bd = sa + 3 * MATB + SWO(row, ks * 2 + b_c);
                    uint32_t p[4];
                    ldm_x4(p, bd);
                    blf[2 * jj][0] = p[0]; blf[2 * jj][1] = p[2];
                    blf[2 * jj + 1][0] = p[1]; blf[2 * jj + 1][1] = p[3];
                }
#pragma unroll
                for (int i = 0; i < 4; i++)
#pragma unroll
                    for (int j = 0; j < 8; j++)
                        mma_f16(acc[i][j], ah[i], blf[j]);
            }
        }
    }
#undef LOADST

    int r0 = lane >> 2, c0 = (lane & 3) * 2;
#pragma unroll
    for (int i = 0; i < 4; i++) {
#pragma unroll
        for (int j = 0; j < 8; j++) {
            int row = by * 128 + warpM + 16 * i + r0;
            int col = bx * 128 + warpN + 8 * j + c0;
#pragma unroll
            for (int half = 0; half < 2; half++) {
                size_t off = (size_t)(row + half * 8) * N + col;
                float v0 = acc[i][j][2 * half];
                float v1 = acc[i][j][2 * half + 1];
                if (EPI == 0) {
                    *(float2*)(C + off) = make_float2(v0, v1);
                } else if (EPI == 1) {
                    float2 rr = *(const float2*)(Res + off);
                    *(float2*)(C + off) = make_float2(v0 + rr.x, v1 + rr.y);
                } else {
                    if (EPI == 2) { v0 = gelu_f(v0); v1 = gelu_f(v1); }
                    __half h0 = __float2half(v0);
                    __half h1 = __float2half(v1);
                    __half l0 = __float2half(v0 - __half2float(h0));
                    __half l1 = __float2half(v1 - __half2float(h1));
                    *(__half2*)(Chi + off) = __halves2half2(h0, h1);
                    *(__half2*)(Clo + off) = __halves2half2(l0, l1);
                }
            }
        }
    }
}

// ---------------- HMMA flash attention (round-10 version) ----------------
#define SWO8(row_, chk_) ((uint32_t)((row_) * 128 + (((chk_) ^ ((row_) & 7)) << 4)))
#define AT_Q   0
#define AT_QL  8192
#define AT_K   16384
#define AT_KL  24576
#define AT_V   32768
#define AT_VL  40960
#define AT_SMEM 49152

__global__ void __launch_bounds__(128) attn_hmma(
    const __half* __restrict__ qkvHi, const __half* __restrict__ qkvLo,
    __half* __restrict__ oHi, __half* __restrict__ oLo)
{
    extern __shared__ char smem[];
    uint32_t sbase = smem_u32(smem);
    int qi = blockIdx.x;
    int bh = blockIdx.y;
    int b = bh >> 4, h = bh & 15;
    int tid = threadIdx.x, wid = tid >> 5, lane = tid & 31;
    int warpM = wid * 16;

    const size_t tokbase = (size_t)b * TSEQ * 3072;
    const __half* qH = qkvHi + tokbase + h * 64;
    const __half* qL = qkvLo + tokbase + h * 64;
    const __half* kH = qH + 1024;
    const __half* kL = qL + 1024;
    const __half* vH = qH + 2048;
    const __half* vL = qL + 2048;

    int lrow = tid >> 1;
    int lc0 = (tid & 1) * 4;

#pragma unroll
    for (int i = 0; i < 4; i++) {
        int chk = lc0 + i;
        size_t g = (size_t)(qi * 64 + lrow) * 3072 + chk * 8;
        cpa16(sbase + AT_Q + SWO8(lrow, chk), qH + g);
        cpa16(sbase + AT_QL + SWO8(lrow, chk), qL + g);
    }
    cp_commit();

    float acc_o[8][4];
#pragma unroll
    for (int j = 0; j < 8; j++)
#pragma unroll
        for (int q = 0; q < 4; q++) acc_o[j][q] = 0.f;
    float mrow[2] = {-1e30f, -1e30f};
    float lrw[2] = {0.f, 0.f};

    int a_r = lane & 15;
    int a_c = lane >> 4;
    int b_r = ((lane >> 3) & 1) * 8 + (lane & 7);
    int b_c = lane >> 4;

    for (int jt = 0; jt <= qi; jt++) {
        __syncthreads();
#pragma unroll
        for (int i = 0; i < 4; i++) {
            int chk = lc0 + i;
            size_t g = (size_t)(jt * 64 + lrow) * 3072 + chk * 8;
            uint32_t soff = SWO8(lrow, chk);
            cpa16(sbase + AT_K + soff, kH + g);
            cpa16(sbase + AT_KL + soff, kL + g);
            cpa16(sbase + AT_V + soff, vH + g);
            cpa16(sbase + AT_VL + soff, vL + g);
        }
        cp_commit();
        cp_wait<0>();
        __syncthreads();

        float s[8][4];
#pragma unroll
        for (int j = 0; j < 8; j++)
#pragma unroll
            for (int q = 0; q < 4; q++) s[j][q] = 0.f;

#pragma unroll
        for (int kc = 0; kc < 4; kc++) {
            uint32_t ah[4], al[4], kf[8][2];
            uint32_t ad = sbase + AT_Q + SWO8(warpM + a_r, kc * 2 + a_c);
            ldm_x4(ah, ad);
            ldm_x4(al, ad + (AT_QL - AT_Q));
#pragma unroll
            for (int jj = 0; jj < 4; jj++) {
                uint32_t bd = sbase + AT_K + SWO8(16 * jj + b_r, kc * 2 + b_c);
                uint32_t q[4];
                ldm_x4(q, bd);
                kf[2 * jj][0] = q[0]; kf[2 * jj][1] = q[2];
                kf[2 * jj + 1][0] = q[1]; kf[2 * jj + 1][1] = q[3];
            }
#pragma unroll
            for (int j = 0; j < 8; j++)
                mma_f16(s[j], ah, kf[j]);
#pragma unroll
            for (int j = 0; j < 8; j++)
                mma_f16(s[j], al, kf[j]);
            uint32_t klf[8][2];
#pragma unroll
            for (int jj = 0; jj < 4; jj++) {
                uint32_t bd = sbase + AT_KL + SWO8(16 * jj + b_r, kc * 2 + b_c);
                uint32_t p[4];
                ldm_x4(p, bd);
                klf[2 * jj][0] = p[0]; klf[2 * jj][1] = p[2];
                klf[2 * jj + 1][0] = p[1]; klf[2 * jj + 1][1] = p[3];
            }
#pragma unroll
            for (int j = 0; j < 8; j++)
                mma_f16(s[j], ah, klf[j]);
        }

        int rA = qi * 64 + warpM + (lane >> 2);
        int cbase = jt * 64 + (lane & 3) * 2;
#pragma unroll
        for (int j = 0; j < 8; j++) {
#pragma unroll
            for (int q = 0; q < 4; q++) {
                float v = s[j][q] * 0.125f;
                if (jt == qi) {
                    int col = cbase + j * 8 + (q & 1);
                    int row = rA + (q >= 2 ? 8 : 0);
                    if (col > row) v = -1e30f;
                }
                s[j][q] = v;
            }
        }

#pragma unroll
        for (int hf = 0; hf < 2; hf++) {
            float mt = -1e30f;
#pragma unroll
            for (int j = 0; j < 8; j++)
                mt = fmaxf(mt, fmaxf(s[j][2 * hf], s[j][2 * hf + 1]));
            mt = fmaxf(mt, __shfl_xor_sync(0xffffffffu, mt, 1));
            mt = fmaxf(mt, __shfl_xor_sync(0xffffffffu, mt, 2));
            float mn = fmaxf(mrow[hf], mt);
            float alpha = __expf(mrow[hf] - mn);
            float ls = 0.f;
#pragma unroll
            for (int j = 0; j < 8; j++) {
                float p0 = __expf(s[j][2 * hf] - mn);
                float p1 = __expf(s[j][2 * hf + 1] - mn);
                s[j][2 * hf] = p0; s[j][2 * hf + 1] = p1;
                ls += p0 + p1;
            }
            ls += __shfl_xor_sync(0xffffffffu, ls, 1);
            ls += __shfl_xor_sync(0xffffffffu, ls, 2);
            lrw[hf] = lrw[hf] * alpha + ls;
            mrow[hf] = mn;
#pragma unroll
            for (int j = 0; j < 8; j++) {
                acc_o[j][2 * hf] *= alpha;
                acc_o[j][2 * hf + 1] *= alpha;
            }
        }

#pragma unroll
        for (int kc = 0; kc < 4; kc++) {
            uint32_t phi[4], plo[4];
            {
                float p00 = s[2 * kc][0], p01 = s[2 * kc][1];
                float p02 = s[2 * kc][2], p03 = s[2 * kc][3];
                float p10 = s[2 * kc + 1][0], p11 = s[2 * kc + 1][1];
                float p12 = s[2 * kc + 1][2], p13 = s[2 * kc + 1][3];
                phi[0] = pack2h(p00, p01);
                phi[1] = pack2h(p02, p03);
                phi[2] = pack2h(p10, p11);
                phi[3] = pack2h(p12, p13);
                __half2 h0 = *(__half2*)&phi[0];
                __half2 h1 = *(__half2*)&phi[1];
                __half2 h2 = *(__half2*)&phi[2];
                __half2 h3 = *(__half2*)&phi[3];
                plo[0] = pack2h(p00 - __half2float(__low2half(h0)), p01 - __half2float(__high2half(h0)));
                plo[1] = pack2h(p02 - __half2float(__low2half(h1)), p03 - __half2float(__high2half(h1)));
                plo[2] = pack2h(p10 - __half2float(__low2half(h2)), p11 - __half2float(__high2half(h2)));
                plo[3] = pack2h(p12 - __half2float(__low2half(h3)), p13 - __half2float(__high2half(h3)));
            }
            uint32_t vfh[8][2], vfl[8][2];
#pragma unroll
            for (int g = 0; g < 4; g++) {
                uint32_t bd = sbase + AT_V + SWO8(kc * 16 + b_r, 2 * g + b_c);
                uint32_t q[4];
                ldm_x4t(q, bd);
                vfh[2 * g][0] = q[0]; vfh[2 * g][1] = q[1];
                vfh[2 * g + 1][0] = q[2]; vfh[2 * g + 1][1] = q[3];
                uint32_t p[4];
                ldm_x4t(p, bd + (AT_VL - AT_V));
                vfl[2 * g][0] = p[0]; vfl[2 * g][1] = p[1];
                vfl[2 * g + 1][0] = p[2]; vfl[2 * g + 1][1] = p[3];
            }
#pragma unroll
            for (int j = 0; j < 8; j++)
                mma_f16(acc_o[j], phi, vfh[j]);
#pragma unroll
            for (int j = 0; j < 8; j++)
                mma_f16(acc_o[j], phi, vfl[j]);
#pragma unroll
            for (int j = 0; j < 8; j++)
                mma_f16(acc_o[j], plo, vfh[j]);
        }
    }

    float inv0 = 1.0f / lrw[0];
    float inv1 = 1.0f / lrw[1];
#pragma unroll
    for (int j = 0; j < 8; j++) {
#pragma unroll
        for (int hf = 0; hf < 2; hf++) {
            int row = b * TSEQ + qi * 64 + warpM + (lane >> 2) + hf * 8;
            int col = h * 64 + j * 8 + (lane & 3) * 2;
            float inv = hf ? inv1 : inv0;
            float v0 = acc_o[j][2 * hf] * inv;
            float v1 = acc_o[j][2 * hf + 1] * inv;
            __half h0 = __float2half(v0);
            __half h1 = __float2half(v1);
            __half l0 = __float2half(v0 - __half2float(h0));
            __half l1 = __float2half(v1 - __half2float(h1));
            size_t off = (size_t)row * DMODEL + col;
            *(__half2*)(oHi + off) = __halves2half2(h0, h1);
            *(__half2*)(oLo + off) = __halves2half2(l0, l1);
        }
    }
}

// ---------------- fp32 -> fp16 hi/lo split ----------------
__global__ __launch_bounds__(256) void split2_kernel(const float* __restrict__ x,
                                                     __half* __restrict__ hi,
                                                     __half* __restrict__ lo, int n4) {
    int i = blockIdx.x * 256 + threadIdx.x;
    if (i >= n4) return;
    float4 v = ((const float4*)x)[i];
    __half h0 = __float2half(v.x), h1 = __float2half(v.y);
    __half h2 = __float2half(v.z), h3 = __float2half(v.w);
    __half l0 = __float2half(v.x - __half2float(h0));
    __half l1 = __float2half(v.y - __half2float(h1));
    __half l2 = __float2half(v.z - __half2float(h2));
    __half l3 = __float2half(v.w - __half2float(h3));
    ((__half2*)hi)[2 * i]     = __halves2half2(h0, h1);
    ((__half2*)hi)[2 * i + 1] = __halves2half2(h2, h3);
    ((__half2*)lo)[2 * i]     = __halves2half2(l0, l1);
    ((__half2*)lo)[2 * i + 1] = __halves2half2(l2, l3);
}

// ---------------- fp32 -> fp16 single (post-router weights) ----------------
__global__ __launch_bounds__(256) void cvt_kernel(const float* __restrict__ x,
                                                  __half* __restrict__ y, int n4) {
    int i = blockIdx.x * 256 + threadIdx.x;
    if (i >= n4) return;
    float4 v = ((const float4*)x)[i];
    ((__half2*)y)[2 * i]     = __floats2half2_rn(v.x, v.y);
    ((__half2*)y)[2 * i + 1] = __floats2half2_rn(v.z, v.w);
}

// ---------------- LayerNorm fused with hi/lo split ----------------
template<int MODE>
__global__ __launch_bounds__(256) void ln_fused(const float* __restrict__ x,
                                                const float* __restrict__ w,
                                                const float* __restrict__ c,
                                                float* __restrict__ outf,
                                                __half* __restrict__ hi,
                                                __half* __restrict__ lo) {
    int row = blockIdx.x;
    int tid = threadIdx.x;
    const float* xr = x + (size_t)row * DMODEL;
    float4 v = *(const float4*)(xr + tid * 4);

    __shared__ float red[8];
    __shared__ float tot;

    float s = v.x + v.y + v.z + v.w;
#pragma unroll
    for (int m = 16; m > 0; m >>= 1) s += __shfl_xor_sync(0xffffffffu, s, m);
    if ((tid & 31) == 0) red[tid >> 5] = s;
    __syncthreads();
    if (tid == 0) { float t = 0.f; for (int i = 0; i < 8; i++) t += red[i]; tot = t; }
    __syncthreads();
    float mean = tot * (1.0f / DMODEL);
    float dx = v.x - mean, dy = v.y - mean, dz = v.z - mean, dw = v.w - mean;
    float s2 = dx * dx + dy * dy + dz * dz + dw * dw;
    __syncthreads();
#pragma unroll
    for (int m = 16; m > 0; m >>= 1) s2 += __shfl_xor_sync(0xffffffffu, s2, m);
    if ((tid & 31) == 0) red[tid >> 5] = s2;
    __syncthreads();
    if (tid == 0) { float t = 0.f; for (int i = 0; i < 8; i++) t += red[i]; tot = t; }
    __syncthreads();
    float inv = rsqrtf(tot * (1.0f / DMODEL) + 1e-5f);

    int d0 = tid * 4;
    float4 w4 = *(const float4*)(w + d0);
    float r0 = dx * inv * w4.x;
    float r1 = dy * inv * w4.y;
    float r2 = dz * inv * w4.z;
    float r3 = dw * inv * w4.w;
    if (MODE == 0) {
        int b = row >> 10;
        float4 c4 = *(const float4*)(c + (size_t)b * DMODEL + d0);
        r0 += c4.x; r1 += c4.y; r2 += c4.z; r3 += c4.w;
    }
    if (MODE == 1)
        *(float4*)(outf + (size_t)row * DMODEL + d0) = make_float4(r0, r1, r2, r3);
    __half h0 = __float2half(r0), h1 = __float2half(r1);
    __half h2 = __float2half(r2), h3 = __float2half(r3);
    __half l0 = __float2half(r0 - __half2float(h0));
    __half l1 = __float2half(r1 - __half2float(h1));
    __half l2 = __float2half(r2 - __half2float(h2));
    __half l3 = __float2half(r3 - __half2float(h3));
    size_t ho = (size_t)row * DMODEL + d0;
    *(__half2*)(hi + ho)     = __halves2half2(h0, h1);
    *(__half2*)(hi + ho + 2) = __halves2half2(h2, h3);
    *(__half2*)(lo + ho)     = __halves2half2(l0, l1);
    *(__half2*)(lo + ho + 2) = __halves2half2(l2, l3);
}

// ---------------- router ----------------
__global__ __launch_bounds__(256) void router_kernel(const float* __restrict__ xn,
                                                     const float* __restrict__ rw,
                                                     int* __restrict__ eidx,
                                                     float* __restrict__ wts) {
    int t = blockIdx.x;
    int tid = threadIdx.x, lane = tid & 31, wp = tid >> 5;
    const float* xr = xn + (size_t)t * DMODEL;
    const float* wr = rw + (size_t)wp * DMODEL;
    float s = 0.f;
    for (int d = lane * 4; d < DMODEL; d += 128) {
        float4 a = *(const float4*)(xr + d);
        float4 b = *(const float4*)(wr + d);
        s += a.x * b.x + a.y * b.y + a.z * b.z + a.w * b.w;
    }
#pragma unroll
    for (int mm = 16; mm > 0; mm >>= 1) s += __shfl_xor_sync(0xffffffffu, s, mm);
    __shared__ float lg[8];
    if (lane == 0) lg[wp] = s;
    __syncthreads();
    if (tid == 0) {
        float mx = lg[0];
        for (int e = 1; e < NE; e++) mx = fmaxf(mx, lg[e]);
        float p[NE]; float sum = 0.f;
        for (int e = 0; e < NE; e++) { p[e] = expf(lg[e] - mx); sum += p[e]; }
        float inv = 1.0f / sum;
        for (int e = 0; e < NE; e++) {
            float v = p[e] * inv + 1e-9f;
            p[e] = fminf(fmaxf(v, 1e-9f), 1.0f - 1e-9f);
        }
        int i0 = 0;
        for (int e = 1; e < NE; e++) if (p[e] > p[i0]) i0 = e;
        int i1 = (i0 == 0) ? 1 : 0;
        for (int e = 0; e < NE; e++) if (e != i0 && p[e] > p[i1]) i1 = e;
        float d2 = 1.0f / (p[i0] + p[i1]);
        eidx[2 * t] = i0; eidx[2 * t + 1] = i1;
        wts[2 * t] = p[i0] * d2; wts[2 * t + 1] = p[i1] * d2;
    }
}

// ---------------- build per-expert CSR + slot->token ----------------
__global__ __launch_bounds__(256) void build_kernel(const int* __restrict__ eidx,
                                                    int* __restrict__ rows,
                                                    int* __restrict__ stok,
                                                    int* __restrict__ tile_e) {
    __shared__ int cnt[NE];
    __shared__ int off[NE];
    int tid = threadIdx.x;
    if (tid < NE) cnt[tid] = 0;
    __syncthreads();
    for (int a = tid; a < BT * 2; a += 256) atomicAdd(&cnt[eidx[a]], 1);
    __syncthreads();
    if (tid == 0) {
        int o = 0;
        for (int e = 0; e < NE; e++) { off[e] = o; o = (o + cnt[e] + 127) & ~127; }
        for (int tt = 0; tt < NTILES; tt++) tile_e[tt] = -1;
        for (int e = 0; e < NE; e++) {
            int nt = (cnt[e] + 127) >> 7;
            int t0 = off[e] >> 7;
            for (int i = 0; i < nt; i++) tile_e[t0 + i] = e;
        }
    }
    __syncthreads();
    if (tid < NE) cnt[tid] = 0;
    for (int r = tid; r < CAP; r += 256) stok[r] = -1;
    __syncthreads();
    for (int a = tid; a < BT * 2; a += 256) {
        int e = eidx[a];
        int pos = atomicAdd(&cnt[e], 1);
        int r = off[e] + pos;
        rows[a] = r;
        stok[r] = a >> 1;
    }
}

// ---------------- combine ----------------
__global__ __launch_bounds__(256) void combine_kernel(const float* __restrict__ xn,
                                                      const float* __restrict__ eo,
                                                      const int* __restrict__ rows,
                                                      const float* __restrict__ wts,
                                                      float* __restrict__ out) {
    int t = blockIdx.x;
    int r0 = rows[2 * t], r1 = rows[2 * t + 1];
    float w0 = wts[2 * t], w1 = wts[2 * t + 1];
    int tid = threadIdx.x;
    float4 a = *(const float4*)(xn + (size_t)t * DMODEL + tid * 4);
    float4 b = *(const float4*)(eo + (size_t)r0 * DMODEL + tid * 4);
    float4 c = *(const float4*)(eo + (size_t)r1 * DMODEL + tid * 4);
    float4 r;
    r.x = a.x + w0 * b.x + w1 * c.x;
    r.y = a.y + w0 * b.y + w1 * c.y;
    r.z = a.z + w0 * b.z + w1 * c.z;
    r.w = a.w + w0 * b.w + w1 * c.w;
    *(float4*)(out + (size_t)t * DMODEL + tid * 4) = r;
}

// ---------------- host launcher ----------------
extern "C" void kernel_launch(void* const* d_in, const int* in_sizes, int n_in,
                              void* d_out, int out_size) {
    const float* x        = (const float*)d_in[0];
    const float* c        = (const float*)d_in[1];
    const float* ln1_w    = (const float*)d_in[2];
    const float* w_qkv    = (const float*)d_in[3];
    const float* w_proj   = (const float*)d_in[4];
    const float* ln2_w    = (const float*)d_in[5];
    const float* router_w = (const float*)d_in[6];
    const float* ew1      = (const float*)d_in[7];
    const float* ew2      = (const float*)d_in[8];
    float* out = (float*)d_out;

    float *p_x2, *p_xn, *p_eo, *p_wts;
    int *p_eidx, *p_rows, *p_stok, *p_te;
    __half *p_aHi, *p_aLo, *p_qkvHi, *p_qkvLo, *p_wHi, *p_wLo, *p_hidHi, *p_hidLo;
    cudaGetSymbolAddress((void**)&p_x2,    g_x2);
    cudaGetSymbolAddress((void**)&p_xn,    g_xn);
    cudaGetSymbolAddress((void**)&p_eo,    g_eo);
    cudaGetSymbolAddress((void**)&p_wts,   g_wts);
    cudaGetSymbolAddress((void**)&p_eidx,  g_eidx);
    cudaGetSymbolAddress((void**)&p_rows,  g_rows);
    cudaGetSymbolAddress((void**)&p_stok,  g_stok);
    cudaGetSymbolAddress((void**)&p_te,    g_tile_e);
    cudaGetSymbolAddress((void**)&p_aHi,   g_aHi);
    cudaGetSymbolAddress((void**)&p_aLo,   g_aLo);
    cudaGetSymbolAddress((void**)&p_qkvHi, g_qkvHi);
    cudaGetSymbolAddress((void**)&p_qkvLo, g_qkvLo);
    cudaGetSymbolAddress((void**)&p_wHi,   g_wHi);
    cudaGetSymbolAddress((void**)&p_wLo,   g_wLo);
    cudaGetSymbolAddress((void**)&p_hidHi, g_hidHi);
    cudaGetSymbolAddress((void**)&p_hidLo, g_hidLo);

    const int SMEM3 = 3 * 4 * MATB;   // 98304
    const int SMEM2 = 4 * 3 * MATB;   // 98304
    cudaFuncSetAttribute((const void*)hmma_gemm<1, 3, 0>, cudaFuncAttributeMaxDynamicSharedMemorySize, SMEM3);
    cudaFuncSetAttribute((const void*)hmma_gemm<3, 3, 0>, cudaFuncAttributeMaxDynamicSharedMemorySize, SMEM3);
    cudaFuncSetAttribute((const void*)hmma_gemm<2, 2, 1>, cudaFuncAttributeMaxDynamicSharedMemorySize, SMEM2);
    cudaFuncSetAttribute((const void*)hmma_gemm<0, 2, 0>, cudaFuncAttributeMaxDynamicSharedMemorySize, SMEM2);
    cudaFuncSetAttribute(attn_hmma, cudaFuncAttributeMaxDynamicSharedMemorySize, AT_SMEM);

    // 1) h = LN1(x)*w + c -> fp16 hi/lo
    ln_fused<0><<<BT, 256>>>(x, ln1_w, c, nullptr, p_aHi, p_aLo);
    split2_kernel<<<(3 * DMODEL * DMODEL / 4 + 255) / 256, 256>>>(w_qkv, p_wHi, p_wLo, 3 * DMODEL * DMODEL / 4);

    // 2) qkv = h @ w_qkv^T (3-term)
    hmma_gemm<3, 3, 0><<<dim3(24, 32), 128, SMEM3>>>(p_aHi, p_aLo, p_wHi, p_wLo, 0, nullptr, nullptr,
                                                     nullptr, nullptr, p_qkvHi, p_qkvLo, 3072, 1024);

    // 3) causal attention
    attn_hmma<<<dim3(16, 64), 128, AT_SMEM>>>(p_qkvHi, p_qkvLo, p_aHi, p_aLo);

    // 4) x2 = x + o @ w_proj^T (3-term)
    split2_kernel<<<(DMODEL * DMODEL / 4 + 255) / 256, 256>>>(w_proj, p_wHi, p_wLo, DMODEL * DMODEL / 4);
    hmma_gemm<1, 3, 0><<<dim3(8, 32), 128, SMEM3>>>(p_aHi, p_aLo, p_wHi, p_wLo, 0, nullptr, nullptr,
                                                    p_x2, x, nullptr, nullptr, 1024, 1024);

    // 5) xn = LN2(x2) -> fp32 + fp16 hi/lo
    ln_fused<1><<<BT, 256>>>(p_x2, ln2_w, nullptr, p_xn, p_aHi, p_aLo);

    // 6) router + CSR + slot->token (fp32: routing exact)
    router_kernel<<<BT, 256>>>(p_xn, router_w, p_eidx, p_wts);
    build_kernel<<<1, 256>>>(p_eidx, p_rows, p_stok, p_te);

    // 7) fc1: hid = gelu(gather(xn) @ w1[e]^T) — A gathered in-kernel (2-term, NSTG=4)
    cvt_kernel<<<(NE * FF * DMODEL / 4 + 255) / 256, 256>>>(ew1, p_wHi, NE * FF * DMODEL / 4);
    hmma_gemm<2, 2, 1><<<dim3(32, NTILES), 128, SMEM2>>>(p_aHi, p_aLo, p_wHi, nullptr,
                                                         (size_t)FF * DMODEL, p_te, p_stok,
                                                         nullptr, nullptr, p_hidHi, p_hidLo, FF, 1024);

    // 8) fc2: eo = hid @ w2[e]^T (2-term, NSTG=4)
    cvt_kernel<<<(NE * DMODEL * FF / 4 + 255) / 256, 256>>>(ew2, p_wHi, NE * DMODEL * FF / 4);
    hmma_gemm<0, 2, 0><<<dim3(8, NTILES), 128, SMEM2>>>(p_hidHi, p_hidLo, p_wHi, nullptr,
                                                        (size_t)DMODEL * FF, p_te, nullptr,
                                                        p_eo, nullptr, nullptr, nullptr, 1024, 4096);

    // 9) out = xn + sum_k w_k * eo
    combine_kernel<<<BT, 256>>>(p_xn, p_eo, p_rows, p_wts, out);
}

// round 14
// speedup vs baseline: 1.8624x; 1.3474x over previous
#include <cuda_runtime.h>
#include <cuda_fp16.h>
#include <math.h>
#include <stdint.h>

// Problem dims
#define BATCH 4
#define TSEQ  1024
#define BT    4096
#define DMODEL 1024
#define NE    8
#define FF    4096
#define CAP   9216
#define NTILES 72

// ---------------- static device scratch ----------------
__device__ float g_x2 [BT * DMODEL];
__device__ float g_xn [BT * DMODEL];
__device__ float g_eo [CAP * DMODEL];
__device__ int   g_eidx[BT * 2];
__device__ float g_wts [BT * 2];
__device__ int   g_rows[BT * 2];
__device__ int   g_stok[CAP];          // slot -> token (-1 = padding)
__device__ int   g_tile_e[NTILES];

// fp16 split scratch
__device__ __half g_aHi [BT * DMODEL];
__device__ __half g_aLo [BT * DMODEL];
__device__ __half g_qkvHi[BT * 3 * DMODEL];
__device__ __half g_qkvLo[BT * 3 * DMODEL];
__device__ __half g_wHi [NE * FF * DMODEL];
__device__ __half g_wLo [NE * FF * DMODEL];
__device__ __half g_hid [CAP * FF];    // single fp16 now

__device__ __forceinline__ float gelu_f(float v) {
    return 0.5f * v * (1.0f + erff(v * 0.70710678118654752f));
}

// ---------------- PTX helpers ----------------
__device__ __forceinline__ uint32_t smem_u32(const void* p) {
    uint32_t a;
    asm("{ .reg .u64 t; cvta.to.shared.u64 t, %1; cvt.u32.u64 %0, t; }" : "=r"(a) : "l"(p));
    return a;
}
__device__ __forceinline__ void cpa16(uint32_t dst, const void* src) {
    asm volatile("cp.async.cg.shared.global [%0], [%1], 16;" :: "r"(dst), "l"(src));
}
__device__ __forceinline__ void cp_commit() { asm volatile("cp.async.commit_group;" ::: "memory"); }
template<int NPEND> __device__ __forceinline__ void cp_wait() {
    asm volatile("cp.async.wait_group %0;" :: "n"(NPEND) : "memory");
}
__device__ __forceinline__ void ldm_x4(uint32_t* r, uint32_t a) {
    asm volatile("ldmatrix.sync.aligned.m8n8.x4.shared.b16 {%0,%1,%2,%3}, [%4];"
        : "=r"(r[0]), "=r"(r[1]), "=r"(r[2]), "=r"(r[3]) : "r"(a));
}
__device__ __forceinline__ void ldm_x4t(uint32_t* r, uint32_t a) {
    asm volatile("ldmatrix.sync.aligned.m8n8.x4.trans.shared.b16 {%0,%1,%2,%3}, [%4];"
        : "=r"(r[0]), "=r"(r[1]), "=r"(r[2]), "=r"(r[3]) : "r"(a));
}
__device__ __forceinline__ void mma_f16(float* d, const uint32_t* a, const uint32_t* b) {
    asm volatile("mma.sync.aligned.m16n8k16.row.col.f32.f16.f16.f32 "
        "{%0,%1,%2,%3}, {%4,%5,%6,%7}, {%8,%9}, {%0,%1,%2,%3};"
        : "+f"(d[0]), "+f"(d[1]), "+f"(d[2]), "+f"(d[3])
        : "r"(a[0]), "r"(a[1]), "r"(a[2]), "r"(a[3]), "r"(b[0]), "r"(b[1]));
}
__device__ __forceinline__ uint32_t pack2h(float x, float y) {
    __half2 h = __halves2half2(__float2half(x), __float2half(y));
    return *(uint32_t*)&h;
}

// ---------------- HMMA NT GEMM ----------------
// TERMS=3: D = Ahi*Bhi + Ahi*Blo + Alo*Bhi  (NSTG=3, 4 mats/stage)  pre-router
// TERMS=2: D = (Ahi+Alo)*B                  (NSTG=4, 3 mats/stage)
// TERMS=1: D = A*B plain fp16               (NSTG=6, 2 mats/stage)  post-router
// GATHER=1: A row g is Ahi[stok[g]]
#define KCH  32
#define MATB  (128 * 64)
#define SWO(row_, chk_) ((uint32_t)((row_) * 64 + (((chk_) ^ (((row_) >> 1) & 3)) << 4)))

// EPI: 0 fp32; 1 fp32+Res; 3 hi/lo; 5 gelu->single fp16
template<int EPI, int TERMS, int GATHER>
__global__ void __launch_bounds__(128, 2) hmma_gemm(
    const __half* __restrict__ Ahi, const __half* __restrict__ Alo,
    const __half* __restrict__ Bhi, const __half* __restrict__ Blo,
    size_t bstride, const int* __restrict__ tile_e,
    const int* __restrict__ stok,
    float* __restrict__ C, const float* __restrict__ Res,
    __half* __restrict__ Chi, __half* __restrict__ Clo,
    int N, int K)
{
    constexpr int NMAT = (TERMS == 3) ? 4 : ((TERMS == 2) ? 3 : 2);
    constexpr int NSTG_T = (TERMS == 3) ? 3 : ((TERMS == 2) ? 4 : 6);
    constexpr uint32_t STGB = NMAT * MATB;
    extern __shared__ char smem[];
    uint32_t sbase = smem_u32(smem);
    int by = blockIdx.y, bx = blockIdx.x;

    const __half* Bh = Bhi;
    const __half* Bl = Blo;
    if (tile_e) {
        int e = tile_e[by];
        if (e < 0) return;
        Bh += (size_t)e * bstride;
        if (TERMS == 3) Bl += (size_t)e * bstride;
    }

    int tid = threadIdx.x, wid = tid >> 5, lane = tid & 31;
    int warpM = (wid >> 1) * 64, warpN = (wid & 1) * 64;

    int lrow = tid >> 2;
    int lchk = tid & 3;
    const __half* pAh = Ahi + (size_t)(by * 128 + lrow) * K + lchk * 8;
    const __half* pAl = Alo + (size_t)(by * 128 + lrow) * K + lchk * 8;
    const __half* pAhp[4];
    if (GATHER) {
#pragma unroll
        for (int p = 0; p < 4; p++) {
            int slot = by * 128 + lrow + p * 32;
            int tok = stok[slot];
            if (tok < 0) tok = 0;
            pAhp[p] = Ahi + (size_t)tok * K + lchk * 8;
        }
    }
    const __half* pB0 = Bh + (size_t)(bx * 128 + lrow) * K + lchk * 8;
    const __half* pB1 = (TERMS == 3) ? (Bl + (size_t)(bx * 128 + lrow) * K + lchk * 8) : nullptr;
    uint32_t so = SWO(lrow, lchk);

#define LOADST(s_) do { \
        uint32_t sb_ = sbase + ((s_) % NSTG_T) * STGB; \
        size_t ko_ = (size_t)(s_) * KCH; \
        _Pragma("unroll") \
        for (int p_ = 0; p_ < 4; p_++) { \
            uint32_t o_ = so + p_ * (32 * 64); \
            size_t g_ = ko_ + (size_t)p_ * 32 * K; \
            const __half* ah_ = GATHER ? (pAhp[p_] + ko_) : (pAh + g_); \
            cpa16(sb_ + o_, ah_); \
            if (TERMS >= 2) cpa16(sb_ + MATB + o_, pAl + g_); \
            cpa16(sb_ + (NMAT - (TERMS == 3 ? 2 : 1)) * MATB + o_, pB0 + g_); \
            if (TERMS == 3) cpa16(sb_ + 3 * MATB + o_, pB1 + g_); \
        } \
        cp_commit(); \
    } while (0)

    float acc[4][8][4];
#pragma unroll
    for (int i = 0; i < 4; i++)
#pragma unroll
        for (int j = 0; j < 8; j++)
#pragma unroll
            for (int q = 0; q < 4; q++) acc[i][j][q] = 0.f;

    int S = K / KCH;
    LOADST(0);
    LOADST(1);
    if (NSTG_T >= 4) LOADST(2);
    if (NSTG_T >= 6) { LOADST(3); LOADST(4); }

    constexpr int BOFF = (TERMS == 3) ? 2 : ((TERMS == 2) ? 2 : 1);  // B matrix index
    int a_r = lane & 15;
    int a_c = lane >> 4;
    int b_r = ((lane >> 3) & 1) * 8 + (lane & 7);
    int b_c = lane >> 4;

    for (int s = 0; s < S; s++) {
        int rem = S - 1 - s;
        if (NSTG_T == 6) {
            if (rem >= 4) cp_wait<4>();
            else if (rem == 3) cp_wait<3>();
            else if (rem == 2) cp_wait<2>();
            else if (rem == 1) cp_wait<1>();
            else cp_wait<0>();
        } else if (NSTG_T == 4) {
            if (rem >= 2) cp_wait<2>();
            else if (rem == 1) cp_wait<1>();
            else cp_wait<0>();
        } else {
            if (rem >= 1) cp_wait<1>();
            else cp_wait<0>();
        }
        __syncthreads();
        if (s + NSTG_T - 1 < S) LOADST(s + NSTG_T - 1);

        uint32_t sa = sbase + (s % NSTG_T) * STGB;
#pragma unroll
        for (int ks = 0; ks < 2; ks++) {
            uint32_t ah[4][4], al[4][4], bhf[8][2];
#pragma unroll
            for (int i = 0; i < 4; i++) {
                int row = warpM + 16 * i + a_r;
                uint32_t ad = sa + SWO(row, ks * 2 + a_c);
                ldm_x4(ah[i], ad);
                if (TERMS >= 2) ldm_x4(al[i], ad + MATB);
            }
#pragma unroll
            for (int jj = 0; jj < 4; jj++) {
                int row = warpN + 16 * jj + b_r;
                uint32_t bd = sa + BOFF * MATB + SWO(row, ks * 2 + b_c);
                uint32_t q[4];
                ldm_x4(q, bd);
                bhf[2 * jj][0] = q[0]; bhf[2 * jj][1] = q[2];
                bhf[2 * jj + 1][0] = q[1]; bhf[2 * jj + 1][1] = q[3];
            }
#pragma unroll
            for (int i = 0; i < 4; i++)
#pragma unroll
                for (int j = 0; j < 8; j++)
                    mma_f16(acc[i][j], ah[i], bhf[j]);
            if (TERMS >= 2) {
#pragma unroll
                for (int i = 0; i < 4; i++)
#pragma unroll
                    for (int j = 0; j < 8; j++)
                        mma_f16(acc[i][j], al[i], bhf[j]);
            }
            if (TERMS == 3) {
                uint32_t blf[8][2];
#pragma unroll
                for (int jj = 0; jj < 4; jj++) {
                    int row = warpN + 16 * jj + b_r;
                    uint32_t bd = sa + 3 * MATB + SWO(row, ks * 2 + b_c);
                    uint32_t p[4];
                    ldm_x4(p, bd);
                    blf[2 * jj][0] = p[0]; blf[2 * jj][1] = p[2];
                    blf[2 * jj + 1][0] = p[1]; blf[2 * jj + 1][1] = p[3];
                }
#pragma unroll
                for (int i = 0; i < 4; i++)
#pragma unroll
                    for (int j = 0; j < 8; j++)
                        mma_f16(acc[i][j], ah[i], blf[j]);
            }
        }
    }
#undef LOADST

    int r0 = lane >> 2, c0 = (lane & 3) * 2;
#pragma unroll
    for (int i = 0; i < 4; i++) {
#pragma unroll
        for (int j = 0; j < 8; j++) {
            int row = by * 128 + warpM + 16 * i + r0;
            int col = bx * 128 + warpN + 8 * j + c0;
#pragma unroll
            for (int half = 0; half < 2; half++) {
                size_t off = (size_t)(row + half * 8) * N + col;
                float v0 = acc[i][j][2 * half];
                float v1 = acc[i][j][2 * half + 1];
                if (EPI == 0) {
                    *(float2*)(C + off) = make_float2(v0, v1);
                } else if (EPI == 1) {
                    float2 rr = *(const float2*)(Res + off);
                    *(float2*)(C + off) = make_float2(v0 + rr.x, v1 + rr.y);
                } else if (EPI == 5) {
                    v0 = gelu_f(v0); v1 = gelu_f(v1);
                    *(__half2*)(Chi + off) = __halves2half2(__float2half(v0), __float2half(v1));
                } else {
                    __half h0 = __float2half(v0);
                    __half h1 = __float2half(v1);
                    __half l0 = __float2half(v0 - __half2float(h0));
                    __half l1 = __float2half(v1 - __half2float(h1));
                    *(__half2*)(Chi + off) = __halves2half2(h0, h1);
                    *(__half2*)(Clo + off) = __halves2half2(l0, l1);
                }
            }
        }
    }
}

// ---------------- HMMA flash attention (round-10 version, unchanged) ----------------
#define SWO8(row_, chk_) ((uint32_t)((row_) * 128 + (((chk_) ^ ((row_) & 7)) << 4)))
#define AT_Q   0
#define AT_QL  8192
#define AT_K   16384
#define AT_KL  24576
#define AT_V   32768
#define AT_VL  40960
#define AT_SMEM 49152

__global__ void __launch_bounds__(128) attn_hmma(
    const __half* __restrict__ qkvHi, const __half* __restrict__ qkvLo,
    __half* __restrict__ oHi, __half* __restrict__ oLo)
{
    extern __shared__ char smem[];
    uint32_t sbase = smem_u32(smem);
    int qi = blockIdx.x;
    int bh = blockIdx.y;
    int b = bh >> 4, h = bh & 15;
    int tid = threadIdx.x, wid = tid >> 5, lane = tid & 31;
    int warpM = wid * 16;

    const size_t tokbase = (size_t)b * TSEQ * 3072;
    const __half* qH = qkvHi + tokbase + h * 64;
    const __half* qL = qkvLo + tokbase + h * 64;
    const __half* kH = qH + 1024;
    const __half* kL = qL + 1024;
    const __half* vH = qH + 2048;
    const __half* vL = qL + 2048;

    int lrow = tid >> 1;
    int lc0 = (tid & 1) * 4;

#pragma unroll
    for (int i = 0; i < 4; i++) {
        int chk = lc0 + i;
        size_t g = (size_t)(qi * 64 + lrow) * 3072 + chk * 8;
        cpa16(sbase + AT_Q + SWO8(lrow, chk), qH + g);
        cpa16(sbase + AT_QL + SWO8(lrow, chk), qL + g);
    }
    cp_commit();

    float acc_o[8][4];
#pragma unroll
    for (int j = 0; j < 8; j++)
#pragma unroll
        for (int q = 0; q < 4; q++) acc_o[j][q] = 0.f;
    float mrow[2] = {-1e30f, -1e30f};
    float lrw[2] = {0.f, 0.f};

    int a_r = lane & 15;
    int a_c = lane >> 4;
    int b_r = ((lane >> 3) & 1) * 8 + (lane & 7);
    int b_c = lane >> 4;

    for (int jt = 0; jt <= qi; jt++) {
        __syncthreads();
#pragma unroll
        for (int i = 0; i < 4; i++) {
            int chk = lc0 + i;
            size_t g = (size_t)(jt * 64 + lrow) * 3072 + chk * 8;
            uint32_t soff = SWO8(lrow, chk);
            cpa16(sbase + AT_K + soff, kH + g);
            cpa16(sbase + AT_KL + soff, kL + g);
            cpa16(sbase + AT_V + soff, vH + g);
            cpa16(sbase + AT_VL + soff, vL + g);
        }
        cp_commit();
        cp_wait<0>();
        __syncthreads();

        float s[8][4];
#pragma unroll
        for (int j = 0; j < 8; j++)
#pragma unroll
            for (int q = 0; q < 4; q++) s[j][q] = 0.f;

#pragma unroll
        for (int kc = 0; kc < 4; kc++) {
            uint32_t ah[4], al[4], kf[8][2];
            uint32_t ad = sbase + AT_Q + SWO8(warpM + a_r, kc * 2 + a_c);
            ldm_x4(ah, ad);
            ldm_x4(al, ad + (AT_QL - AT_Q));
#pragma unroll
            for (int jj = 0; jj < 4; jj++) {
                uint32_t bd = sbase + AT_K + SWO8(16 * jj + b_r, kc * 2 + b_c);
                uint32_t q[4];
                ldm_x4(q, bd);
                kf[2 * jj][0] = q[0]; kf[2 * jj][1] = q[2];
                kf[2 * jj + 1][0] = q[1]; kf[2 * jj + 1][1] = q[3];
            }
#pragma unroll
            for (int j = 0; j < 8; j++)
                mma_f16(s[j], ah, kf[j]);
#pragma unroll
            for (int j = 0; j < 8; j++)
                mma_f16(s[j], al, kf[j]);
            uint32_t klf[8][2];
#pragma unroll
            for (int jj = 0; jj < 4; jj++) {
                uint32_t bd = sbase + AT_KL + SWO8(16 * jj + b_r, kc * 2 + b_c);
                uint32_t p[4];
                ldm_x4(p, bd);
                klf[2 * jj][0] = p[0]; klf[2 * jj][1] = p[2];
                klf[2 * jj + 1][0] = p[1]; klf[2 * jj + 1][1] = p[3];
            }
#pragma unroll
            for (int j = 0; j < 8; j++)
                mma_f16(s[j], ah, klf[j]);
        }

        int rA = qi * 64 + warpM + (lane >> 2);
        int cbase = jt * 64 + (lane & 3) * 2;
#pragma unroll
        for (int j = 0; j < 8; j++) {
#pragma unroll
            for (int q = 0; q < 4; q++) {
                float v = s[j][q] * 0.125f;
                if (jt == qi) {
                    int col = cbase + j * 8 + (q & 1);
                    int row = rA + (q >= 2 ? 8 : 0);
                    if (col > row) v = -1e30f;
                }
                s[j][q] = v;
            }
        }

#pragma unroll
        for (int hf = 0; hf < 2; hf++) {
            float mt = -1e30f;
#pragma unroll
            for (int j = 0; j < 8; j++)
                mt = fmaxf(mt, fmaxf(s[j][2 * hf], s[j][2 * hf + 1]));
            mt = fmaxf(mt, __shfl_xor_sync(0xffffffffu, mt, 1));
            mt = fmaxf(mt, __shfl_xor_sync(0xffffffffu, mt, 2));
            float mn = fmaxf(mrow[hf], mt);
            float alpha = __expf(mrow[hf] - mn);
            float ls = 0.f;
#pragma unroll
            for (int j = 0; j < 8; j++) {
                float p0 = __expf(s[j][2 * hf] - mn);
                float p1 = __expf(s[j][2 * hf + 1] - mn);
                s[j][2 * hf] = p0; s[j][2 * hf + 1] = p1;
                ls += p0 + p1;
            }
            ls += __shfl_xor_sync(0xffffffffu, ls, 1);
            ls += __shfl_xor_sync(0xffffffffu, ls, 2);
            lrw[hf] = lrw[hf] * alpha + ls;
            mrow[hf] = mn;
#pragma unroll
            for (int j = 0; j < 8; j++) {
                acc_o[j][2 * hf] *= alpha;
                acc_o[j][2 * hf + 1] *= alpha;
            }
        }

#pragma unroll
        for (int kc = 0; kc < 4; kc++) {
            uint32_t phi[4], plo[4];
            {
                float p00 = s[2 * kc][0], p01 = s[2 * kc][1];
                float p02 = s[2 * kc][2], p03 = s[2 * kc][3];
                float p10 = s[2 * kc + 1][0], p11 = s[2 * kc + 1][1];
                float p12 = s[2 * kc + 1][2], p13 = s[2 * kc + 1][3];
                phi[0] = pack2h(p00, p01);
                phi[1] = pack2h(p02, p03);
                phi[2] = pack2h(p10, p11);
                phi[3] = pack2h(p12, p13);
                __half2 h0 = *(__half2*)&phi[0];
                __half2 h1 = *(__half2*)&phi[1];
                __half2 h2 = *(__half2*)&phi[2];
                __half2 h3 = *(__half2*)&phi[3];
                plo[0] = pack2h(p00 - __half2float(__low2half(h0)), p01 - __half2float(__high2half(h0)));
                plo[1] = pack2h(p02 - __half2float(__low2half(h1)), p03 - __half2float(__high2half(h1)));
                plo[2] = pack2h(p10 - __half2float(__low2half(h2)), p11 - __half2float(__high2half(h2)));
                plo[3] = pack2h(p12 - __half2float(__low2half(h3)), p13 - __half2float(__high2half(h3)));
            }
            uint32_t vfh[8][2], vfl[8][2];
#pragma unroll
            for (int g = 0; g < 4; g++) {
                uint32_t bd = sbase + AT_V + SWO8(kc * 16 + b_r, 2 * g + b_c);
                uint32_t q[4];
                ldm_x4t(q, bd);
                vfh[2 * g][0] = q[0]; vfh[2 * g][1] = q[1];
                vfh[2 * g + 1][0] = q[2]; vfh[2 * g + 1][1] = q[3];
                uint32_t p[4];
                ldm_x4t(p, bd + (AT_VL - AT_V));
                vfl[2 * g][0] = p[0]; vfl[2 * g][1] = p[1];
                vfl[2 * g + 1][0] = p[2]; vfl[2 * g + 1][1] = p[3];
            }
#pragma unroll
            for (int j = 0; j < 8; j++)
                mma_f16(acc_o[j], phi, vfh[j]);
#pragma unroll
            for (int j = 0; j < 8; j++)
                mma_f16(acc_o[j], phi, vfl[j]);
#pragma unroll
            for (int j = 0; j < 8; j++)
                mma_f16(acc_o[j], plo, vfh[j]);
        }
    }

    float inv0 = 1.0f / lrw[0];
    float inv1 = 1.0f / lrw[1];
#pragma unroll
    for (int j = 0; j < 8; j++) {
#pragma unroll
        for (int hf = 0; hf < 2; hf++) {
            int row = b * TSEQ + qi * 64 + warpM + (lane >> 2) + hf * 8;
            int col = h * 64 + j * 8 + (lane & 3) * 2;
            float inv = hf ? inv1 : inv0;
            float v0 = acc_o[j][2 * hf] * inv;
            float v1 = acc_o[j][2 * hf + 1] * inv;
            __half h0 = __float2half(v0);
            __half h1 = __float2half(v1);
            __half l0 = __float2half(v0 - __half2float(h0));
            __half l1 = __float2half(v1 - __half2float(h1));
            size_t off = (size_t)row * DMODEL + col;
            *(__half2*)(oHi + off) = __halves2half2(h0, h1);
            *(__half2*)(oLo + off) = __halves2half2(l0, l1);
        }
    }
}

// ---------------- fp32 -> fp16 hi/lo split ----------------
__global__ __launch_bounds__(256) void split2_kernel(const float* __restrict__ x,
                                                     __half* __restrict__ hi,
                                                     __half* __restrict__ lo, int n4) {
    int i = blockIdx.x * 256 + threadIdx.x;
    if (i >= n4) return;
    float4 v = ((const float4*)x)[i];
    __half h0 = __float2half(v.x), h1 = __float2half(v.y);
    __half h2 = __float2half(v.z), h3 = __float2half(v.w);
    __half l0 = __float2half(v.x - __half2float(h0));
    __half l1 = __float2half(v.y - __half2float(h1));
    __half l2 = __float2half(v.z - __half2float(h2));
    __half l3 = __float2half(v.w - __half2float(h3));
    ((__half2*)hi)[2 * i]     = __halves2half2(h0, h1);
    ((__half2*)hi)[2 * i + 1] = __halves2half2(h2, h3);
    ((__half2*)lo)[2 * i]     = __halves2half2(l0, l1);
    ((__half2*)lo)[2 * i + 1] = __halves2half2(l2, l3);
}

// ---------------- fp32 -> fp16 single (post-router weights) ----------------
__global__ __launch_bounds__(256) void cvt_kernel(const float* __restrict__ x,
                                                  __half* __restrict__ y, int n4) {
    int i = blockIdx.x * 256 + threadIdx.x;
    if (i >= n4) return;
    float4 v = ((const float4*)x)[i];
    ((__half2*)y)[2 * i]     = __floats2half2_rn(v.x, v.y);
    ((__half2*)y)[2 * i + 1] = __floats2half2_rn(v.z, v.w);
}

// ---------------- LayerNorm fused with hi/lo split ----------------
template<int MODE>
__global__ __launch_bounds__(256) void ln_fused(const float* __restrict__ x,
                                                const float* __restrict__ w,
                                                const float* __restrict__ c,
                                                float* __restrict__ outf,
                                                __half* __restrict__ hi,
                                                __half* __restrict__ lo) {
    int row = blockIdx.x;
    int tid = threadIdx.x;
    const float* xr = x + (size_t)row * DMODEL;
    float4 v = *(const float4*)(xr + tid * 4);

    __shared__ float red[8];
    __shared__ float tot;

    float s = v.x + v.y + v.z + v.w;
#pragma unroll
    for (int m = 16; m > 0; m >>= 1) s += __shfl_xor_sync(0xffffffffu, s, m);
    if ((tid & 31) == 0) red[tid >> 5] = s;
    __syncthreads();
    if (tid == 0) { float t = 0.f; for (int i = 0; i < 8; i++) t += red[i]; tot = t; }
    __syncthreads();
    float mean = tot * (1.0f / DMODEL);
    float dx = v.x - mean, dy = v.y - mean, dz = v.z - mean, dw = v.w - mean;
    float s2 = dx * dx + dy * dy + dz * dz + dw * dw;
    __syncthreads();
#pragma unroll
    for (int m = 16; m > 0; m >>= 1) s2 += __shfl_xor_sync(0xffffffffu, s2, m);
    if ((tid & 31) == 0) red[tid >> 5] = s2;
    __syncthreads();
    if (tid == 0) { float t = 0.f; for (int i = 0; i < 8; i++) t += red[i]; tot = t; }
    __syncthreads();
    float inv = rsqrtf(tot * (1.0f / DMODEL) + 1e-5f);

    int d0 = tid * 4;
    float4 w4 = *(const float4*)(w + d0);
    float r0 = dx * inv * w4.x;
    float r1 = dy * inv * w4.y;
    float r2 = dz * inv * w4.z;
    float r3 = dw * inv * w4.w;
    if (MODE == 0) {
        int b = row >> 10;
        float4 c4 = *(const float4*)(c + (size_t)b * DMODEL + d0);
        r0 += c4.x; r1 += c4.y; r2 += c4.z; r3 += c4.w;
    }
    if (MODE == 1)
        *(float4*)(outf + (size_t)row * DMODEL + d0) = make_float4(r0, r1, r2, r3);
    __half h0 = __float2half(r0), h1 = __float2half(r1);
    __half h2 = __float2half(r2), h3 = __float2half(r3);
    __half l0 = __float2half(r0 - __half2float(h0));
    __half l1 = __float2half(r1 - __half2float(h1));
    __half l2 = __float2half(r2 - __half2float(h2));
    __half l3 = __float2half(r3 - __half2float(h3));
    size_t ho = (size_t)row * DMODEL + d0;
    *(__half2*)(hi + ho)     = __halves2half2(h0, h1);
    *(__half2*)(hi + ho + 2) = __halves2half2(h2, h3);
    *(__half2*)(lo + ho)     = __halves2half2(l0, l1);
    *(__half2*)(lo + ho + 2) = __halves2half2(l2, l3);
}

// ---------------- router ----------------
__global__ __launch_bounds__(256) void router_kernel(const float* __restrict__ xn,
                                                     const float* __restrict__ rw,
                                                     int* __restrict__ eidx,
                                                     float* __restrict__ wts) {
    int t = blockIdx.x;
    int tid = threadIdx.x, lane = tid & 31, wp = tid >> 5;
    const float* xr = xn + (size_t)t * DMODEL;
    const float* wr = rw + (size_t)wp * DMODEL;
    float s = 0.f;
    for (int d = lane * 4; d < DMODEL; d += 128) {
        float4 a = *(const float4*)(xr + d);
        float4 b = *(const float4*)(wr + d);
        s += a.x * b.x + a.y * b.y + a.z * b.z + a.w * b.w;
    }
#pragma unroll
    for (int mm = 16; mm > 0; mm >>= 1) s += __shfl_xor_sync(0xffffffffu, s, mm);
    __shared__ float lg[8];
    if (lane == 0) lg[wp] = s;
    __syncthreads();
    if (tid == 0) {
        float mx = lg[0];
        for (int e = 1; e < NE; e++) mx = fmaxf(mx, lg[e]);
        float p[NE]; float sum = 0.f;
        for (int e = 0; e < NE; e++) { p[e] = expf(lg[e] - mx); sum += p[e]; }
        float inv = 1.0f / sum;
        for (int e = 0; e < NE; e++) {
            float v = p[e] * inv + 1e-9f;
            p[e] = fminf(fmaxf(v, 1e-9f), 1.0f - 1e-9f);
        }
        int i0 = 0;
        for (int e = 1; e < NE; e++) if (p[e] > p[i0]) i0 = e;
        int i1 = (i0 == 0) ? 1 : 0;
        for (int e = 0; e < NE; e++) if (e != i0 && p[e] > p[i1]) i1 = e;
        float d2 = 1.0f / (p[i0] + p[i1]);
        eidx[2 * t] = i0; eidx[2 * t + 1] = i1;
        wts[2 * t] = p[i0] * d2; wts[2 * t + 1] = p[i1] * d2;
    }
}

// ---------------- build per-expert CSR + slot->token ----------------
__global__ __launch_bounds__(256) void build_kernel(const int* __restrict__ eidx,
                                                    int* __restrict__ rows,
                                                    int* __restrict__ stok,
                                                    int* __restrict__ tile_e) {
    __shared__ int cnt[NE];
    __shared__ int off[NE];
    int tid = threadIdx.x;
    if (tid < NE) cnt[tid] = 0;
    __syncthreads();
    for (int a = tid; a < BT * 2; a += 256) atomicAdd(&cnt[eidx[a]], 1);
    __syncthreads();
    if (tid == 0) {
        int o = 0;
        for (int e = 0; e < NE; e++) { off[e] = o; o = (o + cnt[e] + 127) & ~127; }
        for (int tt = 0; tt < NTILES; tt++) tile_e[tt] = -1;
        for (int e = 0; e < NE; e++) {
            int nt = (cnt[e] + 127) >> 7;
            int t0 = off[e] >> 7;
            for (int i = 0; i < nt; i++) tile_e[t0 + i] = e;
        }
    }
    __syncthreads();
    if (tid < NE) cnt[tid] = 0;
    for (int r = tid; r < CAP; r += 256) stok[r] = -1;
    __syncthreads();
    for (int a = tid; a < BT * 2; a += 256) {
        int e = eidx[a];
        int pos = atomicAdd(&cnt[e], 1);
        int r = off[e] + pos;
        rows[a] = r;
        stok[r] = a >> 1;
    }
}

// ---------------- combine ----------------
__global__ __launch_bounds__(256) void combine_kernel(const float* __restrict__ xn,
                                                      const float* __restrict__ eo,
                                                      const int* __restrict__ rows,
                                                      const float* __restrict__ wts,
                                                      float* __restrict__ out) {
    int t = blockIdx.x;
    int r0 = rows[2 * t], r1 = rows[2 * t + 1];
    float w0 = wts[2 * t], w1 = wts[2 * t + 1];
    int tid = threadIdx.x;
    float4 a = *(const float4*)(xn + (size_t)t * DMODEL + tid * 4);
    float4 b = *(const float4*)(eo + (size_t)r0 * DMODEL + tid * 4);
    float4 c = *(const float4*)(eo + (size_t)r1 * DMODEL + tid * 4);
    float4 r;
    r.x = a.x + w0 * b.x + w1 * c.x;
    r.y = a.y + w0 * b.y + w1 * c.y;
    r.z = a.z + w0 * b.z + w1 * c.z;
    r.w = a.w + w0 * b.w + w1 * c.w;
    *(float4*)(out + (size_t)t * DMODEL + tid * 4) = r;
}

// ---------------- host launcher ----------------
extern "C" void kernel_launch(void* const* d_in, const int* in_sizes, int n_in,
                              void* d_out, int out_size) {
    const float* x        = (const float*)d_in[0];
    const float* c        = (const float*)d_in[1];
    const float* ln1_w    = (const float*)d_in[2];
    const float* w_qkv    = (const float*)d_in[3];
    const float* w_proj   = (const float*)d_in[4];
    const float* ln2_w    = (const float*)d_in[5];
    const float* router_w = (const float*)d_in[6];
    const float* ew1      = (const float*)d_in[7];
    const float* ew2      = (const float*)d_in[8];
    float* out = (float*)d_out;

    float *p_x2, *p_xn, *p_eo, *p_wts;
    int *p_eidx, *p_rows, *p_stok, *p_te;
    __half *p_aHi, *p_aLo, *p_qkvHi, *p_qkvLo, *p_wHi, *p_wLo, *p_hid;
    cudaGetSymbolAddress((void**)&p_x2,    g_x2);
    cudaGetSymbolAddress((void**)&p_xn,    g_xn);
    cudaGetSymbolAddress((void**)&p_eo,    g_eo);
    cudaGetSymbolAddress((void**)&p_wts,   g_wts);
    cudaGetSymbolAddress((void**)&p_eidx,  g_eidx);
    cudaGetSymbolAddress((void**)&p_rows,  g_rows);
    cudaGetSymbolAddress((void**)&p_stok,  g_stok);
    cudaGetSymbolAddress((void**)&p_te,    g_tile_e);
    cudaGetSymbolAddress((void**)&p_aHi,   g_aHi);
    cudaGetSymbolAddress((void**)&p_aLo,   g_aLo);
    cudaGetSymbolAddress((void**)&p_qkvHi, g_qkvHi);
    cudaGetSymbolAddress((void**)&p_qkvLo, g_qkvLo);
    cudaGetSymbolAddress((void**)&p_wHi,   g_wHi);
    cudaGetSymbolAddress((void**)&p_wLo,   g_wLo);
    cudaGetSymbolAddress((void**)&p_hid,   g_hid);

    const int SMEM3 = 3 * 4 * MATB;   // 98304
    const int SMEM1 = 6 * 2 * MATB;   // 98304
    cudaFuncSetAttribute((const void*)hmma_gemm<1, 3, 0>, cudaFuncAttributeMaxDynamicSharedMemorySize, SMEM3);
    cudaFuncSetAttribute((const void*)hmma_gemm<3, 3, 0>, cudaFuncAttributeMaxDynamicSharedMemorySize, SMEM3);
    cudaFuncSetAttribute((const void*)hmma_gemm<5, 1, 1>, cudaFuncAttributeMaxDynamicSharedMemorySize, SMEM1);
    cudaFuncSetAttribute((const void*)hmma_gemm<0, 1, 0>, cudaFuncAttributeMaxDynamicSharedMemorySize, SMEM1);
    cudaFuncSetAttribute(attn_hmma, cudaFuncAttributeMaxDynamicSharedMemorySize, AT_SMEM);

    // 1) h = LN1(x)*w + c -> fp16 hi/lo
    ln_fused<0><<<BT, 256>>>(x, ln1_w, c, nullptr, p_aHi, p_aLo);
    split2_kernel<<<(3 * DMODEL * DMODEL / 4 + 255) / 256, 256>>>(w_qkv, p_wHi, p_wLo, 3 * DMODEL * DMODEL / 4);

    // 2) qkv = h @ w_qkv^T (3-term, pre-router precision)
    hmma_gemm<3, 3, 0><<<dim3(24, 32), 128, SMEM3>>>(p_aHi, p_aLo, p_wHi, p_wLo, 0, nullptr, nullptr,
                                                     nullptr, nullptr, p_qkvHi, p_qkvLo, 3072, 1024);

    // 3) causal attention (3-term)
    attn_hmma<<<dim3(16, 64), 128, AT_SMEM>>>(p_qkvHi, p_qkvLo, p_aHi, p_aLo);

    // 4) x2 = x + o @ w_proj^T (3-term)
    split2_kernel<<<(DMODEL * DMODEL / 4 + 255) / 256, 256>>>(w_proj, p_wHi, p_wLo, DMODEL * DMODEL / 4);
    hmma_gemm<1, 3, 0><<<dim3(8, 32), 128, SMEM3>>>(p_aHi, p_aLo, p_wHi, p_wLo, 0, nullptr, nullptr,
                                                    p_x2, x, nullptr, nullptr, 1024, 1024);

    // 5) xn = LN2(x2) -> fp32 + fp16 hi/lo
    ln_fused<1><<<BT, 256>>>(p_x2, ln2_w, nullptr, p_xn, p_aHi, p_aLo);

    // 6) router + CSR + slot->token (fp32: routing exact)
    router_kernel<<<BT, 256>>>(p_xn, router_w, p_eidx, p_wts);
    build_kernel<<<1, 256>>>(p_eidx, p_rows, p_stok, p_te);

    // 7) fc1: hid = gelu(gather(xn) @ w1[e]^T) — 1-term plain fp16, NSTG=6
    cvt_kernel<<<(NE * FF * DMODEL / 4 + 255) / 256, 256>>>(ew1, p_wHi, NE * FF * DMODEL / 4);
    hmma_gemm<5, 1, 1><<<dim3(32, NTILES), 128, SMEM1>>>(p_aHi, nullptr, p_wHi, nullptr,
                                                         (size_t)FF * DMODEL, p_te, p_stok,
                                                         nullptr, nullptr, p_hid, nullptr, FF, 1024);

    // 8) fc2: eo = hid @ w2[e]^T — 1-term plain fp16, NSTG=6
    cvt_kernel<<<(NE * DMODEL * FF / 4 + 255) / 256, 256>>>(ew2, p_wHi, NE * DMODEL * FF / 4);
    hmma_gemm<0, 1, 0><<<dim3(8, NTILES), 128, SMEM1>>>(p_hid, nullptr, p_wHi, nullptr,
                                                        (size_t)DMODEL * FF, p_te, nullptr,
                                                        p_eo, nullptr, nullptr, nullptr, 1024, 4096);

    // 9) out = xn + sum_k w_k * eo
    combine_kernel<<<BT, 256>>>(p_xn, p_eo, p_rows, p_wts, out);
}

// round 15
// speedup vs baseline: 1.8691x; 1.0036x over previous
#include <cuda_runtime.h>
#include <cuda_fp16.h>
#include <math.h>
#include <stdint.h>

// Problem dims
#define BATCH 4
#define TSEQ  1024
#define BT    4096
#define DMODEL 1024
#define NE    8
#define FF    4096
#define CAP   9216
#define NTILES 72

// ---------------- static device scratch ----------------
__device__ float g_x2 [BT * DMODEL];
__device__ float g_xn [BT * DMODEL];
__device__ float g_eo [CAP * DMODEL];
__device__ int   g_eidx[BT * 2];
__device__ float g_wts [BT * 2];
__device__ int   g_rows[BT * 2];
__device__ int   g_stok[CAP];          // slot -> token (-1 = padding)
__device__ int   g_tile_e[NTILES];

// fp16 split scratch
__device__ __half g_aHi [BT * DMODEL];
__device__ __half g_aLo [BT * DMODEL];
__device__ __half g_qkvHi[BT * 3 * DMODEL];
__device__ __half g_qkvLo[BT * 3 * DMODEL];
__device__ __half g_wHi [3 * DMODEL * DMODEL];   // pre-router weights hi (qkv, then proj)
__device__ __half g_wLo [3 * DMODEL * DMODEL];   // pre-router weights lo
__device__ __half g_w1  [NE * FF * DMODEL];      // expert fc1 weights (side stream)
__device__ __half g_w2  [NE * DMODEL * FF];      // expert fc2 weights (side stream)
__device__ __half g_hid [CAP * FF];              // single fp16

__device__ __forceinline__ float gelu_f(float v) {
    return 0.5f * v * (1.0f + erff(v * 0.70710678118654752f));
}

// ---------------- PTX helpers ----------------
__device__ __forceinline__ uint32_t smem_u32(const void* p) {
    uint32_t a;
    asm("{ .reg .u64 t; cvta.to.shared.u64 t, %1; cvt.u32.u64 %0, t; }" : "=r"(a) : "l"(p));
    return a;
}
__device__ __forceinline__ void cpa16(uint32_t dst, const void* src) {
    asm volatile("cp.async.cg.shared.global [%0], [%1], 16;" :: "r"(dst), "l"(src));
}
__device__ __forceinline__ void cp_commit() { asm volatile("cp.async.commit_group;" ::: "memory"); }
template<int NPEND> __device__ __forceinline__ void cp_wait() {
    asm volatile("cp.async.wait_group %0;" :: "n"(NPEND) : "memory");
}
__device__ __forceinline__ void ldm_x4(uint32_t* r, uint32_t a) {
    asm volatile("ldmatrix.sync.aligned.m8n8.x4.shared.b16 {%0,%1,%2,%3}, [%4];"
        : "=r"(r[0]), "=r"(r[1]), "=r"(r[2]), "=r"(r[3]) : "r"(a));
}
__device__ __forceinline__ void ldm_x4t(uint32_t* r, uint32_t a) {
    asm volatile("ldmatrix.sync.aligned.m8n8.x4.trans.shared.b16 {%0,%1,%2,%3}, [%4];"
        : "=r"(r[0]), "=r"(r[1]), "=r"(r[2]), "=r"(r[3]) : "r"(a));
}
__device__ __forceinline__ void mma_f16(float* d, const uint32_t* a, const uint32_t* b) {
    asm volatile("mma.sync.aligned.m16n8k16.row.col.f32.f16.f16.f32 "
        "{%0,%1,%2,%3}, {%4,%5,%6,%7}, {%8,%9}, {%0,%1,%2,%3};"
        : "+f"(d[0]), "+f"(d[1]), "+f"(d[2]), "+f"(d[3])
        : "r"(a[0]), "r"(a[1]), "r"(a[2]), "r"(a[3]), "r"(b[0]), "r"(b[1]));
}
__device__ __forceinline__ uint32_t pack2h(float x, float y) {
    __half2 h = __halves2half2(__float2half(x), __float2half(y));
    return *(uint32_t*)&h;
}

// ---------------- HMMA NT GEMM ----------------
// TERMS=3: D = Ahi*Bhi + Ahi*Blo + Alo*Bhi  (NSTG=3, 4 mats/stage)  pre-router
// TERMS=1: D = A*B plain fp16               (NSTG=6, 2 mats/stage)  post-router
// GATHER=1: A row g is Ahi[stok[g]]
#define KCH  32
#define MATB  (128 * 64)
#define SWO(row_, chk_) ((uint32_t)((row_) * 64 + (((chk_) ^ (((row_) >> 1) & 3)) << 4)))

// EPI: 0 fp32; 1 fp32+Res; 3 hi/lo; 5 gelu->single fp16
template<int EPI, int TERMS, int GATHER>
__global__ void __launch_bounds__(128, 2) hmma_gemm(
    const __half* __restrict__ Ahi, const __half* __restrict__ Alo,
    const __half* __restrict__ Bhi, const __half* __restrict__ Blo,
    size_t bstride, const int* __restrict__ tile_e,
    const int* __restrict__ stok,
    float* __restrict__ C, const float* __restrict__ Res,
    __half* __restrict__ Chi, __half* __restrict__ Clo,
    int N, int K)
{
    constexpr int NMAT = (TERMS == 3) ? 4 : ((TERMS == 2) ? 3 : 2);
    constexpr int NSTG_T = (TERMS == 3) ? 3 : ((TERMS == 2) ? 4 : 6);
    constexpr uint32_t STGB = NMAT * MATB;
    extern __shared__ char smem[];
    uint32_t sbase = smem_u32(smem);
    int by = blockIdx.y, bx = blockIdx.x;

    const __half* Bh = Bhi;
    const __half* Bl = Blo;
    if (tile_e) {
        int e = tile_e[by];
        if (e < 0) return;
        Bh += (size_t)e * bstride;
        if (TERMS == 3) Bl += (size_t)e * bstride;
    }

    int tid = threadIdx.x, wid = tid >> 5, lane = tid & 31;
    int warpM = (wid >> 1) * 64, warpN = (wid & 1) * 64;

    int lrow = tid >> 2;
    int lchk = tid & 3;
    const __half* pAh = Ahi + (size_t)(by * 128 + lrow) * K + lchk * 8;
    const __half* pAl = Alo + (size_t)(by * 128 + lrow) * K + lchk * 8;
    const __half* pAhp[4];
    if (GATHER) {
#pragma unroll
        for (int p = 0; p < 4; p++) {
            int slot = by * 128 + lrow + p * 32;
            int tok = stok[slot];
            if (tok < 0) tok = 0;
            pAhp[p] = Ahi + (size_t)tok * K + lchk * 8;
        }
    }
    const __half* pB0 = Bh + (size_t)(bx * 128 + lrow) * K + lchk * 8;
    const __half* pB1 = (TERMS == 3) ? (Bl + (size_t)(bx * 128 + lrow) * K + lchk * 8) : nullptr;
    uint32_t so = SWO(lrow, lchk);

#define LOADST(s_) do { \
        uint32_t sb_ = sbase + ((s_) % NSTG_T) * STGB; \
        size_t ko_ = (size_t)(s_) * KCH; \
        _Pragma("unroll") \
        for (int p_ = 0; p_ < 4; p_++) { \
            uint32_t o_ = so + p_ * (32 * 64); \
            size_t g_ = ko_ + (size_t)p_ * 32 * K; \
            const __half* ah_ = GATHER ? (pAhp[p_] + ko_) : (pAh + g_); \
            cpa16(sb_ + o_, ah_); \
            if (TERMS >= 2) cpa16(sb_ + MATB + o_, pAl + g_); \
            cpa16(sb_ + (NMAT - (TERMS == 3 ? 2 : 1)) * MATB + o_, pB0 + g_); \
            if (TERMS == 3) cpa16(sb_ + 3 * MATB + o_, pB1 + g_); \
        } \
        cp_commit(); \
    } while (0)

    float acc[4][8][4];
#pragma unroll
    for (int i = 0; i < 4; i++)
#pragma unroll
        for (int j = 0; j < 8; j++)
#pragma unroll
            for (int q = 0; q < 4; q++) acc[i][j][q] = 0.f;

    int S = K / KCH;
    LOADST(0);
    LOADST(1);
    if (NSTG_T >= 4) LOADST(2);
    if (NSTG_T >= 6) { LOADST(3); LOADST(4); }

    constexpr int BOFF = (TERMS == 3) ? 2 : ((TERMS == 2) ? 2 : 1);
    int a_r = lane & 15;
    int a_c = lane >> 4;
    int b_r = ((lane >> 3) & 1) * 8 + (lane & 7);
    int b_c = lane >> 4;

    for (int s = 0; s < S; s++) {
        int rem = S - 1 - s;
        if (NSTG_T == 6) {
            if (rem >= 4) cp_wait<4>();
            else if (rem == 3) cp_wait<3>();
            else if (rem == 2) cp_wait<2>();
            else if (rem == 1) cp_wait<1>();
            else cp_wait<0>();
        } else if (NSTG_T == 4) {
            if (rem >= 2) cp_wait<2>();
            else if (rem == 1) cp_wait<1>();
            else cp_wait<0>();
        } else {
            if (rem >= 1) cp_wait<1>();
            else cp_wait<0>();
        }
        __syncthreads();
        if (s + NSTG_T - 1 < S) LOADST(s + NSTG_T - 1);

        uint32_t sa = sbase + (s % NSTG_T) * STGB;
#pragma unroll
        for (int ks = 0; ks < 2; ks++) {
            uint32_t ah[4][4], al[4][4], bhf[8][2];
#pragma unroll
            for (int i = 0; i < 4; i++) {
                int row = warpM + 16 * i + a_r;
                uint32_t ad = sa + SWO(row, ks * 2 + a_c);
                ldm_x4(ah[i], ad);
                if (TERMS >= 2) ldm_x4(al[i], ad + MATB);
            }
#pragma unroll
            for (int jj = 0; jj < 4; jj++) {
                int row = warpN + 16 * jj + b_r;
                uint32_t bd = sa + BOFF * MATB + SWO(row, ks * 2 + b_c);
                uint32_t q[4];
                ldm_x4(q, bd);
                bhf[2 * jj][0] = q[0]; bhf[2 * jj][1] = q[2];
                bhf[2 * jj + 1][0] = q[1]; bhf[2 * jj + 1][1] = q[3];
            }
#pragma unroll
            for (int i = 0; i < 4; i++)
#pragma unroll
                for (int j = 0; j < 8; j++)
                    mma_f16(acc[i][j], ah[i], bhf[j]);
            if (TERMS >= 2) {
#pragma unroll
                for (int i = 0; i < 4; i++)
#pragma unroll
                    for (int j = 0; j < 8; j++)
                        mma_f16(acc[i][j], al[i], bhf[j]);
            }
            if (TERMS == 3) {
                uint32_t blf[8][2];
#pragma unroll
                for (int jj = 0; jj < 4; jj++) {
                    int row = warpN + 16 * jj + b_r;
                    uint32_t bd = sa + 3 * MATB + SWO(row, ks * 2 + b_c);
                    uint32_t p[4];
                    ldm_x4(p, bd);
                    blf[2 * jj][0] = p[0]; blf[2 * jj][1] = p[2];
                    blf[2 * jj + 1][0] = p[1]; blf[2 * jj + 1][1] = p[3];
                }
#pragma unroll
                for (int i = 0; i < 4; i++)
#pragma unroll
                    for (int j = 0; j < 8; j++)
                        mma_f16(acc[i][j], ah[i], blf[j]);
            }
        }
    }
#undef LOADST

    int r0 = lane >> 2, c0 = (lane & 3) * 2;
#pragma unroll
    for (int i = 0; i < 4; i++) {
#pragma unroll
        for (int j = 0; j < 8; j++) {
            int row = by * 128 + warpM + 16 * i + r0;
            int col = bx * 128 + warpN + 8 * j + c0;
#pragma unroll
            for (int half = 0; half < 2; half++) {
                size_t off = (size_t)(row + half * 8) * N + col;
                float v0 = acc[i][j][2 * half];
                float v1 = acc[i][j][2 * half + 1];
                if (EPI == 0) {
                    *(float2*)(C + off) = make_float2(v0, v1);
                } else if (EPI == 1) {
                    float2 rr = *(const float2*)(Res + off);
                    *(float2*)(C + off) = make_float2(v0 + rr.x, v1 + rr.y);
                } else if (EPI == 5) {
                    v0 = gelu_f(v0); v1 = gelu_f(v1);
                    *(__half2*)(Chi + off) = __halves2half2(__float2half(v0), __float2half(v1));
                } else {
                    __half h0 = __float2half(v0);
                    __half h1 = __float2half(v1);
                    __half l0 = __float2half(v0 - __half2float(h0));
                    __half l1 = __float2half(v1 - __half2float(h1));
                    *(__half2*)(Chi + off) = __halves2half2(h0, h1);
                    *(__half2*)(Clo + off) = __halves2half2(l0, l1);
                }
            }
        }
    }
}

// ---------------- HMMA flash attention (unchanged) ----------------
#define SWO8(row_, chk_) ((uint32_t)((row_) * 128 + (((chk_) ^ ((row_) & 7)) << 4)))
#define AT_Q   0
#define AT_QL  8192
#define AT_K   16384
#define AT_KL  24576
#define AT_V   32768
#define AT_VL  40960
#define AT_SMEM 49152

__global__ void __launch_bounds__(128) attn_hmma(
    const __half* __restrict__ qkvHi, const __half* __restrict__ qkvLo,
    __half* __restrict__ oHi, __half* __restrict__ oLo)
{
    extern __shared__ char smem[];
    uint32_t sbase = smem_u32(smem);
    int qi = blockIdx.x;
    int bh = blockIdx.y;
    int b = bh >> 4, h = bh & 15;
    int tid = threadIdx.x, wid = tid >> 5, lane = tid & 31;
    int warpM = wid * 16;

    const size_t tokbase = (size_t)b * TSEQ * 3072;
    const __half* qH = qkvHi + tokbase + h * 64;
    const __half* qL = qkvLo + tokbase + h * 64;
    const __half* kH = qH + 1024;
    const __half* kL = qL + 1024;
    const __half* vH = qH + 2048;
    const __half* vL = qL + 2048;

    int lrow = tid >> 1;
    int lc0 = (tid & 1) * 4;

#pragma unroll
    for (int i = 0; i < 4; i++) {
        int chk = lc0 + i;
        size_t g = (size_t)(qi * 64 + lrow) * 3072 + chk * 8;
        cpa16(sbase + AT_Q + SWO8(lrow, chk), qH + g);
        cpa16(sbase + AT_QL + SWO8(lrow, chk), qL + g);
    }
    cp_commit();

    float acc_o[8][4];
#pragma unroll
    for (int j = 0; j < 8; j++)
#pragma unroll
        for (int q = 0; q < 4; q++) acc_o[j][q] = 0.f;
    float mrow[2] = {-1e30f, -1e30f};
    float lrw[2] = {0.f, 0.f};

    int a_r = lane & 15;
    int a_c = lane >> 4;
    int b_r = ((lane >> 3) & 1) * 8 + (lane & 7);
    int b_c = lane >> 4;

    for (int jt = 0; jt <= qi; jt++) {
        __syncthreads();
#pragma unroll
        for (int i = 0; i < 4; i++) {
            int chk = lc0 + i;
            size_t g = (size_t)(jt * 64 + lrow) * 3072 + chk * 8;
            uint32_t soff = SWO8(lrow, chk);
            cpa16(sbase + AT_K + soff, kH + g);
            cpa16(sbase + AT_KL + soff, kL + g);
            cpa16(sbase + AT_V + soff, vH + g);
            cpa16(sbase + AT_VL + soff, vL + g);
        }
        cp_commit();
        cp_wait<0>();
        __syncthreads();

        float s[8][4];
#pragma unroll
        for (int j = 0; j < 8; j++)
#pragma unroll
            for (int q = 0; q < 4; q++) s[j][q] = 0.f;

#pragma unroll
        for (int kc = 0; kc < 4; kc++) {
            uint32_t ah[4], al[4], kf[8][2];
            uint32_t ad = sbase + AT_Q + SWO8(warpM + a_r, kc * 2 + a_c);
            ldm_x4(ah, ad);
            ldm_x4(al, ad + (AT_QL - AT_Q));
#pragma unroll
            for (int jj = 0; jj < 4; jj++) {
                uint32_t bd = sbase + AT_K + SWO8(16 * jj + b_r, kc * 2 + b_c);
                uint32_t q[4];
                ldm_x4(q, bd);
                kf[2 * jj][0] = q[0]; kf[2 * jj][1] = q[2];
                kf[2 * jj + 1][0] = q[1]; kf[2 * jj + 1][1] = q[3];
            }
#pragma unroll
            for (int j = 0; j < 8; j++)
                mma_f16(s[j], ah, kf[j]);
#pragma unroll
            for (int j = 0; j < 8; j++)
                mma_f16(s[j], al, kf[j]);
            uint32_t klf[8][2];
#pragma unroll
            for (int jj = 0; jj < 4; jj++) {
                uint32_t bd = sbase + AT_KL + SWO8(16 * jj + b_r, kc * 2 + b_c);
                uint32_t p[4];
                ldm_x4(p, bd);
                klf[2 * jj][0] = p[0]; klf[2 * jj][1] = p[2];
                klf[2 * jj + 1][0] = p[1]; klf[2 * jj + 1][1] = p[3];
            }
#pragma unroll
            for (int j = 0; j < 8; j++)
                mma_f16(s[j], ah, klf[j]);
        }

        int rA = qi * 64 + warpM + (lane >> 2);
        int cbase = jt * 64 + (lane & 3) * 2;
#pragma unroll
        for (int j = 0; j < 8; j++) {
#pragma unroll
            for (int q = 0; q < 4; q++) {
                float v = s[j][q] * 0.125f;
                if (jt == qi) {
                    int col = cbase + j * 8 + (q & 1);
                    int row = rA + (q >= 2 ? 8 : 0);
                    if (col > row) v = -1e30f;
                }
                s[j][q] = v;
            }
        }

#pragma unroll
        for (int hf = 0; hf < 2; hf++) {
            float mt = -1e30f;
#pragma unroll
            for (int j = 0; j < 8; j++)
                mt = fmaxf(mt, fmaxf(s[j][2 * hf], s[j][2 * hf + 1]));
            mt = fmaxf(mt, __shfl_xor_sync(0xffffffffu, mt, 1));
            mt = fmaxf(mt, __shfl_xor_sync(0xffffffffu, mt, 2));
            float mn = fmaxf(mrow[hf], mt);
            float alpha = __expf(mrow[hf] - mn);
            float ls = 0.f;
#pragma unroll
            for (int j = 0; j < 8; j++) {
                float p0 = __expf(s[j][2 * hf] - mn);
                float p1 = __expf(s[j][2 * hf + 1] - mn);
                s[j][2 * hf] = p0; s[j][2 * hf + 1] = p1;
                ls += p0 + p1;
            }
            ls += __shfl_xor_sync(0xffffffffu, ls, 1);
            ls += __shfl_xor_sync(0xffffffffu, ls, 2);
            lrw[hf] = lrw[hf] * alpha + ls;
            mrow[hf] = mn;
#pragma unroll
            for (int j = 0; j < 8; j++) {
                acc_o[j][2 * hf] *= alpha;
                acc_o[j][2 * hf + 1] *= alpha;
            }
        }

#pragma unroll
        for (int kc = 0; kc < 4; kc++) {
            uint32_t phi[4], plo[4];
            {
                float p00 = s[2 * kc][0], p01 = s[2 * kc][1];
                float p02 = s[2 * kc][2], p03 = s[2 * kc][3];
                float p10 = s[2 * kc + 1][0], p11 = s[2 * kc + 1][1];
                float p12 = s[2 * kc + 1][2], p13 = s[2 * kc + 1][3];
                phi[0] = pack2h(p00, p01);
                phi[1] = pack2h(p02, p03);
                phi[2] = pack2h(p10, p11);
                phi[3] = pack2h(p12, p13);
                __half2 h0 = *(__half2*)&phi[0];
                __half2 h1 = *(__half2*)&phi[1];
                __half2 h2 = *(__half2*)&phi[2];
                __half2 h3 = *(__half2*)&phi[3];
                plo[0] = pack2h(p00 - __half2float(__low2half(h0)), p01 - __half2float(__high2half(h0)));
                plo[1] = pack2h(p02 - __half2float(__low2half(h1)), p03 - __half2float(__high2half(h1)));
                plo[2] = pack2h(p10 - __half2float(__low2half(h2)), p11 - __half2float(__high2half(h2)));
                plo[3] = pack2h(p12 - __half2float(__low2half(h3)), p13 - __half2float(__high2half(h3)));
            }
            uint32_t vfh[8][2], vfl[8][2];
#pragma unroll
            for (int g = 0; g < 4; g++) {
                uint32_t bd = sbase + AT_V + SWO8(kc * 16 + b_r, 2 * g + b_c);
                uint32_t q[4];
                ldm_x4t(q, bd);
                vfh[2 * g][0] = q[0]; vfh[2 * g][1] = q[1];
                vfh[2 * g + 1][0] = q[2]; vfh[2 * g + 1][1] = q[3];
                uint32_t p[4];
                ldm_x4t(p, bd + (AT_VL - AT_V));
                vfl[2 * g][0] = p[0]; vfl[2 * g][1] = p[1];
                vfl[2 * g + 1][0] = p[2]; vfl[2 * g + 1][1] = p[3];
            }
#pragma unroll
            for (int j = 0; j < 8; j++)
                mma_f16(acc_o[j], phi, vfh[j]);
#pragma unroll
            for (int j = 0; j < 8; j++)
                mma_f16(acc_o[j], phi, vfl[j]);
#pragma unroll
            for (int j = 0; j < 8; j++)
                mma_f16(acc_o[j], plo, vfh[j]);
        }
    }

    float inv0 = 1.0f / lrw[0];
    float inv1 = 1.0f / lrw[1];
#pragma unroll
    for (int j = 0; j < 8; j++) {
#pragma unroll
        for (int hf = 0; hf < 2; hf++) {
            int row = b * TSEQ + qi * 64 + warpM + (lane >> 2) + hf * 8;
            int col = h * 64 + j * 8 + (lane & 3) * 2;
            float inv = hf ? inv1 : inv0;
            float v0 = acc_o[j][2 * hf] * inv;
            float v1 = acc_o[j][2 * hf + 1] * inv;
            __half h0 = __float2half(v0);
            __half h1 = __float2half(v1);
            __half l0 = __float2half(v0 - __half2float(h0));
            __half l1 = __float2half(v1 - __half2float(h1));
            size_t off = (size_t)row * DMODEL + col;
            *(__half2*)(oHi + off) = __halves2half2(h0, h1);
            *(__half2*)(oLo + off) = __halves2half2(l0, l1);
        }
    }
}

// ---------------- fp32 -> fp16 hi/lo split ----------------
__global__ __launch_bounds__(256) void split2_kernel(const float* __restrict__ x,
                                                     __half* __restrict__ hi,
                                                     __half* __restrict__ lo, int n4) {
    int i = blockIdx.x * 256 + threadIdx.x;
    if (i >= n4) return;
    float4 v = ((const float4*)x)[i];
    __half h0 = __float2half(v.x), h1 = __float2half(v.y);
    __half h2 = __float2half(v.z), h3 = __float2half(v.w);
    __half l0 = __float2half(v.x - __half2float(h0));
    __half l1 = __float2half(v.y - __half2float(h1));
    __half l2 = __float2half(v.z - __half2float(h2));
    __half l3 = __float2half(v.w - __half2float(h3));
    ((__half2*)hi)[2 * i]     = __halves2half2(h0, h1);
    ((__half2*)hi)[2 * i + 1] = __halves2half2(h2, h3);
    ((__half2*)lo)[2 * i]     = __halves2half2(l0, l1);
    ((__half2*)lo)[2 * i + 1] = __halves2half2(l2, l3);
}

// ---------------- fp32 -> fp16 single (post-router weights) ----------------
__global__ __launch_bounds__(256) void cvt_kernel(const float* __restrict__ x,
                                                  __half* __restrict__ y, int n4) {
    int i = blockIdx.x * 256 + threadIdx.x;
    if (i >= n4) return;
    float4 v = ((const float4*)x)[i];
    ((__half2*)y)[2 * i]     = __floats2half2_rn(v.x, v.y);
    ((__half2*)y)[2 * i + 1] = __floats2half2_rn(v.z, v.w);
}

// ---------------- LayerNorm fused with hi/lo split ----------------
template<int MODE>
__global__ __launch_bounds__(256) void ln_fused(const float* __restrict__ x,
                                                const float* __restrict__ w,
                                                const float* __restrict__ c,
                                                float* __restrict__ outf,
                                                __half* __restrict__ hi,
                                                __half* __restrict__ lo) {
    int row = blockIdx.x;
    int tid = threadIdx.x;
    const float* xr = x + (size_t)row * DMODEL;
    float4 v = *(const float4*)(xr + tid * 4);

    __shared__ float red[8];
    __shared__ float tot;

    float s = v.x + v.y + v.z + v.w;
#pragma unroll
    for (int m = 16; m > 0; m >>= 1) s += __shfl_xor_sync(0xffffffffu, s, m);
    if ((tid & 31) == 0) red[tid >> 5] = s;
    __syncthreads();
    if (tid == 0) { float t = 0.f; for (int i = 0; i < 8; i++) t += red[i]; tot = t; }
    __syncthreads();
    float mean = tot * (1.0f / DMODEL);
    float dx = v.x - mean, dy = v.y - mean, dz = v.z - mean, dw = v.w - mean;
    float s2 = dx * dx + dy * dy + dz * dz + dw * dw;
    __syncthreads();
#pragma unroll
    for (int m = 16; m > 0; m >>= 1) s2 += __shfl_xor_sync(0xffffffffu, s2, m);
    if ((tid & 31) == 0) red[tid >> 5] = s2;
    __syncthreads();
    if (tid == 0) { float t = 0.f; for (int i = 0; i < 8; i++) t += red[i]; tot = t; }
    __syncthreads();
    float inv = rsqrtf(tot * (1.0f / DMODEL) + 1e-5f);

    int d0 = tid * 4;
    float4 w4 = *(const float4*)(w + d0);
    float r0 = dx * inv * w4.x;
    float r1 = dy * inv * w4.y;
    float r2 = dz * inv * w4.z;
    float r3 = dw * inv * w4.w;
    if (MODE == 0) {
        int b = row >> 10;
        float4 c4 = *(const float4*)(c + (size_t)b * DMODEL + d0);
        r0 += c4.x; r1 += c4.y; r2 += c4.z; r3 += c4.w;
    }
    if (MODE == 1)
        *(float4*)(outf + (size_t)row * DMODEL + d0) = make_float4(r0, r1, r2, r3);
    __half h0 = __float2half(r0), h1 = __float2half(r1);
    __half h2 = __float2half(r2), h3 = __float2half(r3);
    __half l0 = __float2half(r0 - __half2float(h0));
    __half l1 = __float2half(r1 - __half2float(h1));
    __half l2 = __float2half(r2 - __half2float(h2));
    __half l3 = __float2half(r3 - __half2float(h3));
    size_t ho = (size_t)row * DMODEL + d0;
    *(__half2*)(hi + ho)     = __halves2half2(h0, h1);
    *(__half2*)(hi + ho + 2) = __halves2half2(h2, h3);
    *(__half2*)(lo + ho)     = __halves2half2(l0, l1);
    *(__half2*)(lo + ho + 2) = __halves2half2(l2, l3);
}

// ---------------- router ----------------
__global__ __launch_bounds__(256) void router_kernel(const float* __restrict__ xn,
                                                     const float* __restrict__ rw,
                                                     int* __restrict__ eidx,
                                                     float* __restrict__ wts) {
    int t = blockIdx.x;
    int tid = threadIdx.x, lane = tid & 31, wp = tid >> 5;
    const float* xr = xn + (size_t)t * DMODEL;
    const float* wr = rw + (size_t)wp * DMODEL;
    float s = 0.f;
    for (int d = lane * 4; d < DMODEL; d += 128) {
        float4 a = *(const float4*)(xr + d);
        float4 b = *(const float4*)(wr + d);
        s += a.x * b.x + a.y * b.y + a.z * b.z + a.w * b.w;
    }
#pragma unroll
    for (int mm = 16; mm > 0; mm >>= 1) s += __shfl_xor_sync(0xffffffffu, s, mm);
    __shared__ float lg[8];
    if (lane == 0) lg[wp] = s;
    __syncthreads();
    if (tid == 0) {
        float mx = lg[0];
        for (int e = 1; e < NE; e++) mx = fmaxf(mx, lg[e]);
        float p[NE]; float sum = 0.f;
        for (int e = 0; e < NE; e++) { p[e] = expf(lg[e] - mx); sum += p[e]; }
        float inv = 1.0f / sum;
        for (int e = 0; e < NE; e++) {
            float v = p[e] * inv + 1e-9f;
            p[e] = fminf(fmaxf(v, 1e-9f), 1.0f - 1e-9f);
        }
        int i0 = 0;
        for (int e = 1; e < NE; e++) if (p[e] > p[i0]) i0 = e;
        int i1 = (i0 == 0) ? 1 : 0;
        for (int e = 0; e < NE; e++) if (e != i0 && p[e] > p[i1]) i1 = e;
        float d2 = 1.0f / (p[i0] + p[i1]);
        eidx[2 * t] = i0; eidx[2 * t + 1] = i1;
        wts[2 * t] = p[i0] * d2; wts[2 * t + 1] = p[i1] * d2;
    }
}

// ---------------- build per-expert CSR + slot->token ----------------
__global__ __launch_bounds__(256) void build_kernel(const int* __restrict__ eidx,
                                                    int* __restrict__ rows,
                                                    int* __restrict__ stok,
                                                    int* __restrict__ tile_e) {
    __shared__ int cnt[NE];
    __shared__ int off[NE];
    int tid = threadIdx.x;
    if (tid < NE) cnt[tid] = 0;
    __syncthreads();
    for (int a = tid; a < BT * 2; a += 256) atomicAdd(&cnt[eidx[a]], 1);
    __syncthreads();
    if (tid == 0) {
        int o = 0;
        for (int e = 0; e < NE; e++) { off[e] = o; o = (o + cnt[e] + 127) & ~127; }
        for (int tt = 0; tt < NTILES; tt++) tile_e[tt] = -1;
        for (int e = 0; e < NE; e++) {
            int nt = (cnt[e] + 127) >> 7;
            int t0 = off[e] >> 7;
            for (int i = 0; i < nt; i++) tile_e[t0 + i] = e;
        }
    }
    __syncthreads();
    if (tid < NE) cnt[tid] = 0;
    for (int r = tid; r < CAP; r += 256) stok[r] = -1;
    __syncthreads();
    for (int a = tid; a < BT * 2; a += 256) {
        int e = eidx[a];
        int pos = atomicAdd(&cnt[e], 1);
        int r = off[e] + pos;
        rows[a] = r;
        stok[r] = a >> 1;
    }
}

// ---------------- combine ----------------
__global__ __launch_bounds__(256) void combine_kernel(const float* __restrict__ xn,
                                                      const float* __restrict__ eo,
                                                      const int* __restrict__ rows,
                                                      const float* __restrict__ wts,
                                                      float* __restrict__ out) {
    int t = blockIdx.x;
    int r0 = rows[2 * t], r1 = rows[2 * t + 1];
    float w0 = wts[2 * t], w1 = wts[2 * t + 1];
    int tid = threadIdx.x;
    float4 a = *(const float4*)(xn + (size_t)t * DMODEL + tid * 4);
    float4 b = *(const float4*)(eo + (size_t)r0 * DMODEL + tid * 4);
    float4 c = *(const float4*)(eo + (size_t)r1 * DMODEL + tid * 4);
    float4 r;
    r.x = a.x + w0 * b.x + w1 * c.x;
    r.y = a.y + w0 * b.y + w1 * c.y;
    r.z = a.z + w0 * b.z + w1 * c.z;
    r.w = a.w + w0 * b.w + w1 * c.w;
    *(float4*)(out + (size_t)t * DMODEL + tid * 4) = r;
}

// ---------------- host launcher ----------------
extern "C" void kernel_launch(void* const* d_in, const int* in_sizes, int n_in,
                              void* d_out, int out_size) {
    const float* x        = (const float*)d_in[0];
    const float* c        = (const float*)d_in[1];
    const float* ln1_w    = (const float*)d_in[2];
    const float* w_qkv    = (const float*)d_in[3];
    const float* w_proj   = (const float*)d_in[4];
    const float* ln2_w    = (const float*)d_in[5];
    const float* router_w = (const float*)d_in[6];
    const float* ew1      = (const float*)d_in[7];
    const float* ew2      = (const float*)d_in[8];
    float* out = (float*)d_out;

    float *p_x2, *p_xn, *p_eo, *p_wts;
    int *p_eidx, *p_rows, *p_stok, *p_te;
    __half *p_aHi, *p_aLo, *p_qkvHi, *p_qkvLo, *p_wHi, *p_wLo, *p_w1, *p_w2, *p_hid;
    cudaGetSymbolAddress((void**)&p_x2,    g_x2);
    cudaGetSymbolAddress((void**)&p_xn,    g_xn);
    cudaGetSymbolAddress((void**)&p_eo,    g_eo);
    cudaGetSymbolAddress((void**)&p_wts,   g_wts);
    cudaGetSymbolAddress((void**)&p_eidx,  g_eidx);
    cudaGetSymbolAddress((void**)&p_rows,  g_rows);
    cudaGetSymbolAddress((void**)&p_stok,  g_stok);
    cudaGetSymbolAddress((void**)&p_te,    g_tile_e);
    cudaGetSymbolAddress((void**)&p_aHi,   g_aHi);
    cudaGetSymbolAddress((void**)&p_aLo,   g_aLo);
    cudaGetSymbolAddress((void**)&p_qkvHi, g_qkvHi);
    cudaGetSymbolAddress((void**)&p_qkvLo, g_qkvLo);
    cudaGetSymbolAddress((void**)&p_wHi,   g_wHi);
    cudaGetSymbolAddress((void**)&p_wLo,   g_wLo);
    cudaGetSymbolAddress((void**)&p_w1,    g_w1);
    cudaGetSymbolAddress((void**)&p_w2,    g_w2);
    cudaGetSymbolAddress((void**)&p_hid,   g_hid);

    const int SMEM3 = 3 * 4 * MATB;   // 98304
    const int SMEM1 = 6 * 2 * MATB;   // 98304
    cudaFuncSetAttribute((const void*)hmma_gemm<1, 3, 0>, cudaFuncAttributeMaxDynamicSharedMemorySize, SMEM3);
    cudaFuncSetAttribute((const void*)hmma_gemm<3, 3, 0>, cudaFuncAttributeMaxDynamicSharedMemorySize, SMEM3);
    cudaFuncSetAttribute((const void*)hmma_gemm<5, 1, 1>, cudaFuncAttributeMaxDynamicSharedMemorySize, SMEM1);
    cudaFuncSetAttribute((const void*)hmma_gemm<0, 1, 0>, cudaFuncAttributeMaxDynamicSharedMemorySize, SMEM1);
    cudaFuncSetAttribute(attn_hmma, cudaFuncAttributeMaxDynamicSharedMemorySize, AT_SMEM);

    // side stream for expert-weight conversion (fork/join, graph-capturable)
    cudaStream_t sW;
    cudaEvent_t evF, evJ;
    cudaStreamCreateWithFlags(&sW, cudaStreamNonBlocking);
    cudaEventCreateWithFlags(&evF, cudaEventDisableTiming);
    cudaEventCreateWithFlags(&evJ, cudaEventDisableTiming);

    // fork: expert weight cvts run concurrently with the whole pre-router path
    cudaEventRecord(evF, 0);
    cudaStreamWaitEvent(sW, evF, 0);
    cvt_kernel<<<(NE * FF * DMODEL / 4 + 255) / 256, 256, 0, sW>>>(ew1, p_w1, NE * FF * DMODEL / 4);
    cvt_kernel<<<(NE * DMODEL * FF / 4 + 255) / 256, 256, 0, sW>>>(ew2, p_w2, NE * DMODEL * FF / 4);
    cudaEventRecord(evJ, sW);

    // 1) h = LN1(x)*w + c -> fp16 hi/lo
    ln_fused<0><<<BT, 256>>>(x, ln1_w, c, nullptr, p_aHi, p_aLo);
    split2_kernel<<<(3 * DMODEL * DMODEL / 4 + 255) / 256, 256>>>(w_qkv, p_wHi, p_wLo, 3 * DMODEL * DMODEL / 4);

    // 2) qkv = h @ w_qkv^T (3-term, pre-router precision)
    hmma_gemm<3, 3, 0><<<dim3(24, 32), 128, SMEM3>>>(p_aHi, p_aLo, p_wHi, p_wLo, 0, nullptr, nullptr,
                                                     nullptr, nullptr, p_qkvHi, p_qkvLo, 3072, 1024);

    // 3) causal attention (3-term)
    attn_hmma<<<dim3(16, 64), 128, AT_SMEM>>>(p_qkvHi, p_qkvLo, p_aHi, p_aLo);

    // 4) x2 = x + o @ w_proj^T (3-term)
    split2_kernel<<<(DMODEL * DMODEL / 4 + 255) / 256, 256>>>(w_proj, p_wHi, p_wLo, DMODEL * DMODEL / 4);
    hmma_gemm<1, 3, 0><<<dim3(8, 32), 128, SMEM3>>>(p_aHi, p_aLo, p_wHi, p_wLo, 0, nullptr, nullptr,
                                                    p_x2, x, nullptr, nullptr, 1024, 1024);

    // 5) xn = LN2(x2) -> fp32 + fp16 hi/lo
    ln_fused<1><<<BT, 256>>>(p_x2, ln2_w, nullptr, p_xn, p_aHi, p_aLo);

    // 6) router + CSR + slot->token (fp32: routing exact)
    router_kernel<<<BT, 256>>>(p_xn, router_w, p_eidx, p_wts);
    build_kernel<<<1, 256>>>(p_eidx, p_rows, p_stok, p_te);

    // join: expert weights ready before fc1
    cudaStreamWaitEvent(0, evJ, 0);

    // 7) fc1: hid = gelu(gather(xn) @ w1[e]^T) — 1-term, NSTG=6, in-kernel gather
    hmma_gemm<5, 1, 1><<<dim3(32, NTILES), 128, SMEM1>>>(p_aHi, nullptr, p_w1, nullptr,
                                                         (size_t)FF * DMODEL, p_te, p_stok,
                                                         nullptr, nullptr, p_hid, nullptr, FF, 1024);

    // 8) fc2: eo = hid @ w2[e]^T — 1-term, NSTG=6
    hmma_gemm<0, 1, 0><<<dim3(8, NTILES), 128, SMEM1>>>(p_hid, nullptr, p_w2, nullptr,
                                                        (size_t)DMODEL * FF, p_te, nullptr,
                                                        p_eo, nullptr, nullptr, nullptr, 1024, 4096);

    // 9) out = xn + sum_k w_k * eo
    combine_kernel<<<BT, 256>>>(p_xn, p_eo, p_rows, p_wts, out);
}

// round 17
// speedup vs baseline: 1.8753x; 1.0033x over previous
#include <cuda_runtime.h>
#include <cuda_fp16.h>
#include <math.h>
#include <stdint.h>

// Problem dims
#define BATCH 4
#define TSEQ  1024
#define BT    4096
#define DMODEL 1024
#define NE    8
#define FF    4096
#define CAP   9216
#define NTILES 72

// ---------------- static device scratch ----------------
__device__ float g_x2 [BT * DMODEL];
__device__ int   g_eidx[BT * 2];
__device__ float g_wts [BT * 2];
__device__ int   g_stok[CAP];          // slot -> token (-1 = padding)
__device__ float g_sw  [CAP];          // slot -> combine weight
__device__ int   g_tile_e[NTILES];

// fp16 split scratch
__device__ __half g_aHi [BT * DMODEL];
__device__ __half g_aLo [BT * DMODEL];
__device__ __half g_qkvHi[BT * 3 * DMODEL];
__device__ __half g_qkvLo[BT * 3 * DMODEL];
__device__ __half g_wHi [3 * DMODEL * DMODEL];
__device__ __half g_wLo [3 * DMODEL * DMODEL];
__device__ __half g_w1  [NE * FF * DMODEL];
__device__ __half g_w2  [NE * DMODEL * FF];
__device__ __half g_hid [CAP * FF];

__device__ __forceinline__ float gelu_f(float v) {
    return 0.5f * v * (1.0f + erff(v * 0.70710678118654752f));
}

// ---------------- PTX helpers ----------------
__device__ __forceinline__ uint32_t smem_u32(const void* p) {
    uint32_t a;
    asm("{ .reg .u64 t; cvta.to.shared.u64 t, %1; cvt.u32.u64 %0, t; }" : "=r"(a) : "l"(p));
    return a;
}
__device__ __forceinline__ void cpa16(uint32_t dst, const void* src) {
    asm volatile("cp.async.cg.shared.global [%0], [%1], 16;" :: "r"(dst), "l"(src));
}
__device__ __forceinline__ void cp_commit() { asm volatile("cp.async.commit_group;" ::: "memory"); }
template<int NPEND> __device__ __forceinline__ void cp_wait() {
    asm volatile("cp.async.wait_group %0;" :: "n"(NPEND) : "memory");
}
__device__ __forceinline__ void ldm_x4(uint32_t* r, uint32_t a) {
    asm volatile("ldmatrix.sync.aligned.m8n8.x4.shared.b16 {%0,%1,%2,%3}, [%4];"
        : "=r"(r[0]), "=r"(r[1]), "=r"(r[2]), "=r"(r[3]) : "r"(a));
}
__device__ __forceinline__ void ldm_x4t(uint32_t* r, uint32_t a) {
    asm volatile("ldmatrix.sync.aligned.m8n8.x4.trans.shared.b16 {%0,%1,%2,%3}, [%4];"
        : "=r"(r[0]), "=r"(r[1]), "=r"(r[2]), "=r"(r[3]) : "r"(a));
}
__device__ __forceinline__ void mma_f16(float* d, const uint32_t* a, const uint32_t* b) {
    asm volatile("mma.sync.aligned.m16n8k16.row.col.f32.f16.f16.f32 "
        "{%0,%1,%2,%3}, {%4,%5,%6,%7}, {%8,%9}, {%0,%1,%2,%3};"
        : "+f"(d[0]), "+f"(d[1]), "+f"(d[2]), "+f"(d[3])
        : "r"(a[0]), "r"(a[1]), "r"(a[2]), "r"(a[3]), "r"(b[0]), "r"(b[1]));
}
__device__ __forceinline__ uint32_t pack2h(float x, float y) {
    __half2 h = __halves2half2(__float2half(x), __float2half(y));
    return *(uint32_t*)&h;
}

// ---------------- HMMA NT GEMM ----------------
// TERMS=3: D = Ahi*Bhi + Ahi*Blo + Alo*Bhi  (NSTG=3, 4 mats/stage)  pre-router
// TERMS=1: D = A*B plain fp16               (NSTG=6, 2 mats/stage)  post-router
// GATHER=1: A row g is Ahi[stok[g]]
#define KCH  32
#define MATB  (128 * 64)
#define SWO(row_, chk_) ((uint32_t)((row_) * 64 + (((chk_) ^ (((row_) >> 1) & 3)) << 4)))

// EPI: 0 fp32; 1 fp32+Res; 3 hi/lo; 4 scatter-atomic; 5 gelu->single fp16
template<int EPI, int TERMS, int GATHER>
__global__ void __launch_bounds__(128, 2) hmma_gemm(
    const __half* __restrict__ Ahi, const __half* __restrict__ Alo,
    const __half* __restrict__ Bhi, const __half* __restrict__ Blo,
    size_t bstride, const int* __restrict__ tile_e,
    const int* __restrict__ stok, const float* __restrict__ sw,
    float* __restrict__ C, const float* __restrict__ Res,
    __half* __restrict__ Chi, __half* __restrict__ Clo,
    int N, int K)
{
    constexpr int NMAT = (TERMS == 3) ? 4 : ((TERMS == 2) ? 3 : 2);
    constexpr int NSTG_T = (TERMS == 3) ? 3 : ((TERMS == 2) ? 4 : 6);
    constexpr uint32_t STGB = NMAT * MATB;
    extern __shared__ char smem[];
    uint32_t sbase = smem_u32(smem);
    int by = blockIdx.y, bx = blockIdx.x;

    const __half* Bh = Bhi;
    const __half* Bl = Blo;
    if (tile_e) {
        int e = tile_e[by];
        if (e < 0) return;
        Bh += (size_t)e * bstride;
        if (TERMS == 3) Bl += (size_t)e * bstride;
    }

    int tid = threadIdx.x, wid = tid >> 5, lane = tid & 31;
    int warpM = (wid >> 1) * 64, warpN = (wid & 1) * 64;

    int lrow = tid >> 2;
    int lchk = tid & 3;
    const __half* pAh = Ahi + (size_t)(by * 128 + lrow) * K + lchk * 8;
    const __half* pAl = Alo + (size_t)(by * 128 + lrow) * K + lchk * 8;
    const __half* pAhp[4];
    if (GATHER) {
#pragma unroll
        for (int p = 0; p < 4; p++) {
            int slot = by * 128 + lrow + p * 32;
            int tok = stok[slot];
            if (tok < 0) tok = 0;
            pAhp[p] = Ahi + (size_t)tok * K + lchk * 8;
        }
    }
    const __half* pB0 = Bh + (size_t)(bx * 128 + lrow) * K + lchk * 8;
    const __half* pB1 = (TERMS == 3) ? (Bl + (size_t)(bx * 128 + lrow) * K + lchk * 8) : nullptr;
    uint32_t so = SWO(lrow, lchk);

#define LOADST(s_) do { \
        uint32_t sb_ = sbase + ((s_) % NSTG_T) * STGB; \
        size_t ko_ = (size_t)(s_) * KCH; \
        _Pragma("unroll") \
        for (int p_ = 0; p_ < 4; p_++) { \
            uint32_t o_ = so + p_ * (32 * 64); \
            size_t g_ = ko_ + (size_t)p_ * 32 * K; \
            const __half* ah_ = GATHER ? (pAhp[p_] + ko_) : (pAh + g_); \
            cpa16(sb_ + o_, ah_); \
            if (TERMS >= 2) cpa16(sb_ + MATB + o_, pAl + g_); \
            cpa16(sb_ + (NMAT - (TERMS == 3 ? 2 : 1)) * MATB + o_, pB0 + g_); \
            if (TERMS == 3) cpa16(sb_ + 3 * MATB + o_, pB1 + g_); \
        } \
        cp_commit(); \
    } while (0)

    float acc[4][8][4];
#pragma unroll
    for (int i = 0; i < 4; i++)
#pragma unroll
        for (int j = 0; j < 8; j++)
#pragma unroll
            for (int q = 0; q < 4; q++) acc[i][j][q] = 0.f;

    int S = K / KCH;
    LOADST(0);
    LOADST(1);
    if (NSTG_T >= 4) LOADST(2);
    if (NSTG_T >= 6) { LOADST(3); LOADST(4); }

    constexpr int BOFF = (TERMS == 3) ? 2 : ((TERMS == 2) ? 2 : 1);
    int a_r = lane & 15;
    int a_c = lane >> 4;
    int b_r = ((lane >> 3) & 1) * 8 + (lane & 7);
    int b_c = lane >> 4;

    for (int s = 0; s < S; s++) {
        int rem = S - 1 - s;
        if (NSTG_T == 6) {
            if (rem >= 4) cp_wait<4>();
            else if (rem == 3) cp_wait<3>();
            else if (rem == 2) cp_wait<2>();
            else if (rem == 1) cp_wait<1>();
            else cp_wait<0>();
        } else if (NSTG_T == 4) {
            if (rem >= 2) cp_wait<2>();
            else if (rem == 1) cp_wait<1>();
            else cp_wait<0>();
        } else {
            if (rem >= 1) cp_wait<1>();
            else cp_wait<0>();
        }
        __syncthreads();
        if (s + NSTG_T - 1 < S) LOADST(s + NSTG_T - 1);

        uint32_t sa = sbase + (s % NSTG_T) * STGB;
#pragma unroll
        for (int ks = 0; ks < 2; ks++) {
            uint32_t ah[4][4], al[4][4], bhf[8][2];
#pragma unroll
            for (int i = 0; i < 4; i++) {
                int row = warpM + 16 * i + a_r;
                uint32_t ad = sa + SWO(row, ks * 2 + a_c);
                ldm_x4(ah[i], ad);
                if (TERMS >= 2) ldm_x4(al[i], ad + MATB);
            }
#pragma unroll
            for (int jj = 0; jj < 4; jj++) {
                int row = warpN + 16 * jj + b_r;
                uint32_t bd = sa + BOFF * MATB + SWO(row, ks * 2 + b_c);
                uint32_t q[4];
                ldm_x4(q, bd);
                bhf[2 * jj][0] = q[0]; bhf[2 * jj][1] = q[2];
                bhf[2 * jj + 1][0] = q[1]; bhf[2 * jj + 1][1] = q[3];
            }
#pragma unroll
            for (int i = 0; i < 4; i++)
#pragma unroll
                for (int j = 0; j < 8; j++)
                    mma_f16(acc[i][j], ah[i], bhf[j]);
            if (TERMS >= 2) {
#pragma unroll
                for (int i = 0; i < 4; i++)
#pragma unroll
                    for (int j = 0; j < 8; j++)
                        mma_f16(acc[i][j], al[i], bhf[j]);
            }
            if (TERMS == 3) {
                uint32_t blf[8][2];
#pragma unroll
                for (int jj = 0; jj < 4; jj++) {
                    int row = warpN + 16 * jj + b_r;
                    uint32_t bd = sa + 3 * MATB + SWO(row, ks * 2 + b_c);
                    uint32_t p[4];
                    ldm_x4(p, bd);
                    blf[2 * jj][0] = p[0]; blf[2 * jj][1] = p[2];
                    blf[2 * jj + 1][0] = p[1]; blf[2 * jj + 1][1] = p[3];
                }
#pragma unroll
                for (int i = 0; i < 4; i++)
#pragma unroll
                    for (int j = 0; j < 8; j++)
                        mma_f16(acc[i][j], ah[i], blf[j]);
            }
        }
    }
#undef LOADST

    int r0 = lane >> 2, c0 = (lane & 3) * 2;
    if (EPI == 4) {
        // fc2 scatter: out[tok] += w_slot * acc  (out pre-filled with xn)
#pragma unroll
        for (int i = 0; i < 4; i++) {
#pragma unroll
            for (int half = 0; half < 2; half++) {
                int row = by * 128 + warpM + 16 * i + r0 + half * 8;
                int tok = stok[row];
                if (tok < 0) continue;
                float wt = sw[row];
                float* ob = C + (size_t)tok * DMODEL;
#pragma unroll
                for (int j = 0; j < 8; j++) {
                    int col = bx * 128 + warpN + 8 * j + c0;
                    atomicAdd(ob + col,     wt * acc[i][j][2 * half]);
                    atomicAdd(ob + col + 1, wt * acc[i][j][2 * half + 1]);
                }
            }
        }
        return;
    }
#pragma unroll
    for (int i = 0; i < 4; i++) {
#pragma unroll
        for (int j = 0; j < 8; j++) {
            int row = by * 128 + warpM + 16 * i + r0;
            int col = bx * 128 + warpN + 8 * j + c0;
#pragma unroll
            for (int half = 0; half < 2; half++) {
                size_t off = (size_t)(row + half * 8) * N + col;
                float v0 = acc[i][j][2 * half];
                float v1 = acc[i][j][2 * half + 1];
                if (EPI == 0) {
                    *(float2*)(C + off) = make_float2(v0, v1);
                } else if (EPI == 1) {
                    float2 rr = *(const float2*)(Res + off);
                    *(float2*)(C + off) = make_float2(v0 + rr.x, v1 + rr.y);
                } else if (EPI == 5) {
                    v0 = gelu_f(v0); v1 = gelu_f(v1);
                    *(__half2*)(Chi + off) = __halves2half2(__float2half(v0), __float2half(v1));
                } else {
                    __half h0 = __float2half(v0);
                    __half h1 = __float2half(v1);
                    __half l0 = __float2half(v0 - __half2float(h0));
                    __half l1 = __float2half(v1 - __half2float(h1));
                    *(__half2*)(Chi + off) = __halves2half2(h0, h1);
                    *(__half2*)(Clo + off) = __halves2half2(l0, l1);
                }
            }
        }
    }
}

// ---------------- HMMA flash attention (unchanged) ----------------
#define SWO8(row_, chk_) ((uint32_t)((row_) * 128 + (((chk_) ^ ((row_) & 7)) << 4)))
#define AT_Q   0
#define AT_QL  8192
#define AT_K   16384
#define AT_KL  24576
#define AT_V   32768
#define AT_VL  40960
#define AT_SMEM 49152

__global__ void __launch_bounds__(128) attn_hmma(
    const __half* __restrict__ qkvHi, const __half* __restrict__ qkvLo,
    __half* __restrict__ oHi, __half* __restrict__ oLo)
{
    extern __shared__ char smem[];
    uint32_t sbase = smem_u32(smem);
    int qi = blockIdx.x;
    int bh = blockIdx.y;
    int b = bh >> 4, h = bh & 15;
    int tid = threadIdx.x, wid = tid >> 5, lane = tid & 31;
    int warpM = wid * 16;

    const size_t tokbase = (size_t)b * TSEQ * 3072;
    const __half* qH = qkvHi + tokbase + h * 64;
    const __half* qL = qkvLo + tokbase + h * 64;
    const __half* kH = qH + 1024;
    const __half* kL = qL + 1024;
    const __half* vH = qH + 2048;
    const __half* vL = qL + 2048;

    int lrow = tid >> 1;
    int lc0 = (tid & 1) * 4;

#pragma unroll
    for (int i = 0; i < 4; i++) {
        int chk = lc0 + i;
        size_t g = (size_t)(qi * 64 + lrow) * 3072 + chk * 8;
        cpa16(sbase + AT_Q + SWO8(lrow, chk), qH + g);
        cpa16(sbase + AT_QL + SWO8(lrow, chk), qL + g);
    }
    cp_commit();

    float acc_o[8][4];
#pragma unroll
    for (int j = 0; j < 8; j++)
#pragma unroll
        for (int q = 0; q < 4; q++) acc_o[j][q] = 0.f;
    float mrow[2] = {-1e30f, -1e30f};
    float lrw[2] = {0.f, 0.f};

    int a_r = lane & 15;
    int a_c = lane >> 4;
    int b_r = ((lane >> 3) & 1) * 8 + (lane & 7);
    int b_c = lane >> 4;

    for (int jt = 0; jt <= qi; jt++) {
        __syncthreads();
#pragma unroll
        for (int i = 0; i < 4; i++) {
            int chk = lc0 + i;
            size_t g = (size_t)(jt * 64 + lrow) * 3072 + chk * 8;
            uint32_t soff = SWO8(lrow, chk);
            cpa16(sbase + AT_K + soff, kH + g);
            cpa16(sbase + AT_KL + soff, kL + g);
            cpa16(sbase + AT_V + soff, vH + g);
            cpa16(sbase + AT_VL + soff, vL + g);
        }
        cp_commit();
        cp_wait<0>();
        __syncthreads();

        float s[8][4];
#pragma unroll
        for (int j = 0; j < 8; j++)
#pragma unroll
            for (int q = 0; q < 4; q++) s[j][q] = 0.f;

#pragma unroll
        for (int kc = 0; kc < 4; kc++) {
            uint32_t ah[4], al[4], kf[8][2];
            uint32_t ad = sbase + AT_Q + SWO8(warpM + a_r, kc * 2 + a_c);
            ldm_x4(ah, ad);
            ldm_x4(al, ad + (AT_QL - AT_Q));
#pragma unroll
            for (int jj = 0; jj < 4; jj++) {
                uint32_t bd = sbase + AT_K + SWO8(16 * jj + b_r, kc * 2 + b_c);
                uint32_t q[4];
                ldm_x4(q, bd);
                kf[2 * jj][0] = q[0]; kf[2 * jj][1] = q[2];
                kf[2 * jj + 1][0] = q[1]; kf[2 * jj + 1][1] = q[3];
            }
#pragma unroll
            for (int j = 0; j < 8; j++)
                mma_f16(s[j], ah, kf[j]);
#pragma unroll
            for (int j = 0; j < 8; j++)
                mma_f16(s[j], al, kf[j]);
            uint32_t klf[8][2];
#pragma unroll
            for (int jj = 0; jj < 4; jj++) {
                uint32_t bd = sbase + AT_KL + SWO8(16 * jj + b_r, kc * 2 + b_c);
                uint32_t p[4];
                ldm_x4(p, bd);
                klf[2 * jj][0] = p[0]; klf[2 * jj][1] = p[2];
                klf[2 * jj + 1][0] = p[1]; klf[2 * jj + 1][1] = p[3];
            }
#pragma unroll
            for (int j = 0; j < 8; j++)
                mma_f16(s[j], ah, klf[j]);
        }

        int rA = qi * 64 + warpM + (lane >> 2);
        int cbase = jt * 64 + (lane & 3) * 2;
#pragma unroll
        for (int j = 0; j < 8; j++) {
#pragma unroll
            for (int q = 0; q < 4; q++) {
                float v = s[j][q] * 0.125f;
                if (jt == qi) {
                    int col = cbase + j * 8 + (q & 1);
                    int row = rA + (q >= 2 ? 8 : 0);
                    if (col > row) v = -1e30f;
                }
                s[j][q] = v;
            }
        }

#pragma unroll
        for (int hf = 0; hf < 2; hf++) {
            float mt = -1e30f;
#pragma unroll
            for (int j = 0; j < 8; j++)
                mt = fmaxf(mt, fmaxf(s[j][2 * hf], s[j][2 * hf + 1]));
            mt = fmaxf(mt, __shfl_xor_sync(0xffffffffu, mt, 1));
            mt = fmaxf(mt, __shfl_xor_sync(0xffffffffu, mt, 2));
            float mn = fmaxf(mrow[hf], mt);
            float alpha = __expf(mrow[hf] - mn);
            float ls = 0.f;
#pragma unroll
            for (int j = 0; j < 8; j++) {
                float p0 = __expf(s[j][2 * hf] - mn);
                float p1 = __expf(s[j][2 * hf + 1] - mn);
                s[j][2 * hf] = p0; s[j][2 * hf + 1] = p1;
                ls += p0 + p1;
            }
            ls += __shfl_xor_sync(0xffffffffu, ls, 1);
            ls += __shfl_xor_sync(0xffffffffu, ls, 2);
            lrw[hf] = lrw[hf] * alpha + ls;
            mrow[hf] = mn;
#pragma unroll
            for (int j = 0; j < 8; j++) {
                acc_o[j][2 * hf] *= alpha;
                acc_o[j][2 * hf + 1] *= alpha;
            }
        }

#pragma unroll
        for (int kc = 0; kc < 4; kc++) {
            uint32_t phi[4], plo[4];
            {
                float p00 = s[2 * kc][0], p01 = s[2 * kc][1];
                float p02 = s[2 * kc][2], p03 = s[2 * kc][3];
                float p10 = s[2 * kc + 1][0], p11 = s[2 * kc + 1][1];
                float p12 = s[2 * kc + 1][2], p13 = s[2 * kc + 1][3];
                phi[0] = pack2h(p00, p01);
                phi[1] = pack2h(p02, p03);
                phi[2] = pack2h(p10, p11);
                phi[3] = pack2h(p12, p13);
                __half2 h0 = *(__half2*)&phi[0];
                __half2 h1 = *(__half2*)&phi[1];
                __half2 h2 = *(__half2*)&phi[2];
                __half2 h3 = *(__half2*)&phi[3];
                plo[0] = pack2h(p00 - __half2float(__low2half(h0)), p01 - __half2float(__high2half(h0)));
                plo[1] = pack2h(p02 - __half2float(__low2half(h1)), p03 - __half2float(__high2half(h1)));
                plo[2] = pack2h(p10 - __half2float(__low2half(h2)), p11 - __half2float(__high2half(h2)));
                plo[3] = pack2h(p12 - __half2float(__low2half(h3)), p13 - __half2float(__high2half(h3)));
            }
            uint32_t vfh[8][2], vfl[8][2];
#pragma unroll
            for (int g = 0; g < 4; g++) {
                uint32_t bd = sbase + AT_V + SWO8(kc * 16 + b_r, 2 * g + b_c);
                uint32_t q[4];
                ldm_x4t(q, bd);
                vfh[2 * g][0] = q[0]; vfh[2 * g][1] = q[1];
                vfh[2 * g + 1][0] = q[2]; vfh[2 * g + 1][1] = q[3];
                uint32_t p[4];
                ldm_x4t(p, bd + (AT_VL - AT_V));
                vfl[2 * g][0] = p[0]; vfl[2 * g][1] = p[1];
                vfl[2 * g + 1][0] = p[2]; vfl[2 * g + 1][1] = p[3];
            }
#pragma unroll
            for (int j = 0; j < 8; j++)
                mma_f16(acc_o[j], phi, vfh[j]);
#pragma unroll
            for (int j = 0; j < 8; j++)
                mma_f16(acc_o[j], phi, vfl[j]);
#pragma unroll
            for (int j = 0; j < 8; j++)
                mma_f16(acc_o[j], plo, vfh[j]);
        }
    }

    float inv0 = 1.0f / lrw[0];
    float inv1 = 1.0f / lrw[1];
#pragma unroll
    for (int j = 0; j < 8; j++) {
#pragma unroll
        for (int hf = 0; hf < 2; hf++) {
            int row = b * TSEQ + qi * 64 + warpM + (lane >> 2) + hf * 8;
            int col = h * 64 + j * 8 + (lane & 3) * 2;
            float inv = hf ? inv1 : inv0;
            float v0 = acc_o[j][2 * hf] * inv;
            float v1 = acc_o[j][2 * hf + 1] * inv;
            __half h0 = __float2half(v0);
            __half h1 = __float2half(v1);
            __half l0 = __float2half(v0 - __half2float(h0));
            __half l1 = __float2half(v1 - __half2float(h1));
            size_t off = (size_t)row * DMODEL + col;
            *(__half2*)(oHi + off) = __halves2half2(h0, h1);
            *(__half2*)(oLo + off) = __halves2half2(l0, l1);
        }
    }
}

// ---------------- fp32 -> fp16 hi/lo split ----------------
__global__ __launch_bounds__(256) void split2_kernel(const float* __restrict__ x,
                                                     __half* __restrict__ hi,
                                                     __half* __restrict__ lo, int n4) {
    int i = blockIdx.x * 256 + threadIdx.x;
    if (i >= n4) return;
    float4 v = ((const float4*)x)[i];
    __half h0 = __float2half(v.x), h1 = __float2half(v.y);
    __half h2 = __float2half(v.z), h3 = __float2half(v.w);
    __half l0 = __float2half(v.x - __half2float(h0));
    __half l1 = __float2half(v.y - __half2float(h1));
    __half l2 = __float2half(v.z - __half2float(h2));
    __half l3 = __float2half(v.w - __half2float(h3));
    ((__half2*)hi)[2 * i]     = __halves2half2(h0, h1);
    ((__half2*)hi)[2 * i + 1] = __halves2half2(h2, h3);
    ((__half2*)lo)[2 * i]     = __halves2half2(l0, l1);
    ((__half2*)lo)[2 * i + 1] = __halves2half2(l2, l3);
}

// ---------------- fp32 -> fp16 single (post-router weights) ----------------
__global__ __launch_bounds__(256) void cvt_kernel(const float* __restrict__ x,
                                                  __half* __restrict__ y, int n4) {
    int i = blockIdx.x * 256 + threadIdx.x;
    if (i >= n4) return;
    float4 v = ((const float4*)x)[i];
    ((__half2*)y)[2 * i]     = __floats2half2_rn(v.x, v.y);
    ((__half2*)y)[2 * i + 1] = __floats2half2_rn(v.z, v.w);
}

// ---------------- LayerNorm fused with hi/lo split ----------------
template<int MODE>
__global__ __launch_bounds__(256) void ln_fused(const float* __restrict__ x,
                                                const float* __restrict__ w,
                                                const float* __restrict__ c,
                                                float* __restrict__ outf,
                                                __half* __restrict__ hi,
                                                __half* __restrict__ lo) {
    int row = blockIdx.x;
    int tid = threadIdx.x;
    const float* xr = x + (size_t)row * DMODEL;
    float4 v = *(const float4*)(xr + tid * 4);

    __shared__ float red[8];
    __shared__ float tot;

    float s = v.x + v.y + v.z + v.w;
#pragma unroll
    for (int m = 16; m > 0; m >>= 1) s += __shfl_xor_sync(0xffffffffu, s, m);
    if ((tid & 31) == 0) red[tid >> 5] = s;
    __syncthreads();
    if (tid == 0) { float t = 0.f; for (int i = 0; i < 8; i++) t += red[i]; tot = t; }
    __syncthreads();
    float mean = tot * (1.0f / DMODEL);
    float dx = v.x - mean, dy = v.y - mean, dz = v.z - mean, dw = v.w - mean;
    float s2 = dx * dx + dy * dy + dz * dz + dw * dw;
    __syncthreads();
#pragma unroll
    for (int m = 16; m > 0; m >>= 1) s2 += __shfl_xor_sync(0xffffffffu, s2, m);
    if ((tid & 31) == 0) red[tid >> 5] = s2;
    __syncthreads();
    if (tid == 0) { float t = 0.f; for (int i = 0; i < 8; i++) t += red[i]; tot = t; }
    __syncthreads();
    float inv = rsqrtf(tot * (1.0f / DMODEL) + 1e-5f);

    int d0 = tid * 4;
    float4 w4 = *(const float4*)(w + d0);
    float r0 = dx * inv * w4.x;
    float r1 = dy * inv * w4.y;
    float r2 = dz * inv * w4.z;
    float r3 = dw * inv * w4.w;
    if (MODE == 0) {
        int b = row >> 10;
        float4 c4 = *(const float4*)(c + (size_t)b * DMODEL + d0);
        r0 += c4.x; r1 += c4.y; r2 += c4.z; r3 += c4.w;
    }
    if (MODE == 1)
        *(float4*)(outf + (size_t)row * DMODEL + d0) = make_float4(r0, r1, r2, r3);
    __half h0 = __float2half(r0), h1 = __float2half(r1);
    __half h2 = __float2half(r2), h3 = __float2half(r3);
    __half l0 = __float2half(r0 - __half2float(h0));
    __half l1 = __float2half(r1 - __half2float(h1));
    __half l2 = __float2half(r2 - __half2float(h2));
    __half l3 = __float2half(r3 - __half2float(h3));
    size_t ho = (size_t)row * DMODEL + d0;
    *(__half2*)(hi + ho)     = __halves2half2(h0, h1);
    *(__half2*)(hi + ho + 2) = __halves2half2(h2, h3);
    *(__half2*)(lo + ho)     = __halves2half2(l0, l1);
    *(__half2*)(lo + ho + 2) = __halves2half2(l2, l3);
}

// ---------------- router ----------------
__global__ __launch_bounds__(256) void router_kernel(const float* __restrict__ xn,
                                                     const float* __restrict__ rw,
                                                     int* __restrict__ eidx,
                                                     float* __restrict__ wts) {
    int t = blockIdx.x;
    int tid = threadIdx.x, lane = tid & 31, wp = tid >> 5;
    const float* xr = xn + (size_t)t * DMODEL;
    const float* wr = rw + (size_t)wp * DMODEL;
    float s = 0.f;
    for (int d = lane * 4; d < DMODEL; d += 128) {
        float4 a = *(const float4*)(xr + d);
        float4 b = *(const float4*)(wr + d);
        s += a.x * b.x + a.y * b.y + a.z * b.z + a.w * b.w;
    }
#pragma unroll
    for (int mm = 16; mm > 0; mm >>= 1) s += __shfl_xor_sync(0xffffffffu, s, mm);
    __shared__ float lg[8];
    if (lane == 0) lg[wp] = s;
    __syncthreads();
    if (tid == 0) {
        float mx = lg[0];
        for (int e = 1; e < NE; e++) mx = fmaxf(mx, lg[e]);
        float p[NE]; float sum = 0.f;
        for (int e = 0; e < NE; e++) { p[e] = expf(lg[e] - mx); sum += p[e]; }
        float inv = 1.0f / sum;
        for (int e = 0; e < NE; e++) {
            float v = p[e] * inv + 1e-9f;
            p[e] = fminf(fmaxf(v, 1e-9f), 1.0f - 1e-9f);
        }
        int i0 = 0;
        for (int e = 1; e < NE; e++) if (p[e] > p[i0]) i0 = e;
        int i1 = (i0 == 0) ? 1 : 0;
        for (int e = 0; e < NE; e++) if (e != i0 && p[e] > p[i1]) i1 = e;
        float d2 = 1.0f / (p[i0] + p[i1]);
        eidx[2 * t] = i0; eidx[2 * t + 1] = i1;
        wts[2 * t] = p[i0] * d2; wts[2 * t + 1] = p[i1] * d2;
    }
}

// ---------------- build slot tables ----------------
__global__ __launch_bounds__(256) void build_kernel(const int* __restrict__ eidx,
                                                    const float* __restrict__ wts,
                                                    int* __restrict__ stok,
                                                    float* __restrict__ sw,
                                                    int* __restrict__ tile_e) {
    __shared__ int cnt[NE];
    __shared__ int off[NE];
    int tid = threadIdx.x;
    if (tid < NE) cnt[tid] = 0;
    __syncthreads();
    for (int a = tid; a < BT * 2; a += 256) atomicAdd(&cnt[eidx[a]], 1);
    __syncthreads();
    if (tid == 0) {
        int o = 0;
        for (int e = 0; e < NE; e++) { off[e] = o; o = (o + cnt[e] + 127) & ~127; }
        for (int tt = 0; tt < NTILES; tt++) tile_e[tt] = -1;
        for (int e = 0; e < NE; e++) {
            int nt = (cnt[e] + 127) >> 7;
            int t0 = off[e] >> 7;
            for (int i = 0; i < nt; i++) tile_e[t0 + i] = e;
        }
    }
    __syncthreads();
    if (tid < NE) cnt[tid] = 0;
    for (int r = tid; r < CAP; r += 256) stok[r] = -1;
    __syncthreads();
    for (int a = tid; a < BT * 2; a += 256) {
        int e = eidx[a];
        int pos = atomicAdd(&cnt[e], 1);
        int r = off[e] + pos;
        stok[r] = a >> 1;
        sw[r] = wts[a];
    }
}

// ---------------- host launcher ----------------
extern "C" void kernel_launch(void* const* d_in, const int* in_sizes, int n_in,
                              void* d_out, int out_size) {
    const float* x        = (const float*)d_in[0];
    const float* c        = (const float*)d_in[1];
    const float* ln1_w    = (const float*)d_in[2];
    const float* w_qkv    = (const float*)d_in[3];
    const float* w_proj   = (const float*)d_in[4];
    const float* ln2_w    = (const float*)d_in[5];
    const float* router_w = (const float*)d_in[6];
    const float* ew1      = (const float*)d_in[7];
    const float* ew2      = (const float*)d_in[8];
    float* out = (float*)d_out;

    float *p_x2, *p_wts, *p_sw;
    int *p_eidx, *p_stok, *p_te;
    __half *p_aHi, *p_aLo, *p_qkvHi, *p_qkvLo, *p_wHi, *p_wLo, *p_w1, *p_w2, *p_hid;
    cudaGetSymbolAddress((void**)&p_x2,    g_x2);
    cudaGetSymbolAddress((void**)&p_wts,   g_wts);
    cudaGetSymbolAddress((void**)&p_sw,    g_sw);
    cudaGetSymbolAddress((void**)&p_eidx,  g_eidx);
    cudaGetSymbolAddress((void**)&p_stok,  g_stok);
    cudaGetSymbolAddress((void**)&p_te,    g_tile_e);
    cudaGetSymbolAddress((void**)&p_aHi,   g_aHi);
    cudaGetSymbolAddress((void**)&p_aLo,   g_aLo);
    cudaGetSymbolAddress((void**)&p_qkvHi, g_qkvHi);
    cudaGetSymbolAddress((void**)&p_qkvLo, g_qkvLo);
    cudaGetSymbolAddress((void**)&p_wHi,   g_wHi);
    cudaGetSymbolAddress((void**)&p_wLo,   g_wLo);
    cudaGetSymbolAddress((void**)&p_w1,    g_w1);
    cudaGetSymbolAddress((void**)&p_w2,    g_w2);
    cudaGetSymbolAddress((void**)&p_hid,   g_hid);

    const int SMEM3 = 3 * 4 * MATB;   // 98304
    const int SMEM1 = 6 * 2 * MATB;   // 98304
    cudaFuncSetAttribute((const void*)hmma_gemm<1, 3, 0>, cudaFuncAttributeMaxDynamicSharedMemorySize, SMEM3);
    cudaFuncSetAttribute((const void*)hmma_gemm<3, 3, 0>, cudaFuncAttributeMaxDynamicSharedMemorySize, SMEM3);
    cudaFuncSetAttribute((const void*)hmma_gemm<5, 1, 1>, cudaFuncAttributeMaxDynamicSharedMemorySize, SMEM1);
    cudaFuncSetAttribute((const void*)hmma_gemm<4, 1, 0>, cudaFuncAttributeMaxDynamicSharedMemorySize, SMEM1);
    cudaFuncSetAttribute(attn_hmma, cudaFuncAttributeMaxDynamicSharedMemorySize, AT_SMEM);

    // side stream for expert-weight conversion (fork/join, graph-capturable)
    cudaStream_t sW;
    cudaEvent_t evF, evJ;
    cudaStreamCreateWithFlags(&sW, cudaStreamNonBlocking);
    cudaEventCreateWithFlags(&evF, cudaEventDisableTiming);
    cudaEventCreateWithFlags(&evJ, cudaEventDisableTiming);

    cudaEventRecord(evF, 0);
    cudaStreamWaitEvent(sW, evF, 0);
    cvt_kernel<<<(NE * FF * DMODEL / 4 + 255) / 256, 256, 0, sW>>>(ew1, p_w1, NE * FF * DMODEL / 4);
    cvt_kernel<<<(NE * DMODEL * FF / 4 + 255) / 256, 256, 0, sW>>>(ew2, p_w2, NE * DMODEL * FF / 4);
    cudaEventRecord(evJ, sW);

    // 1) h = LN1(x)*w + c -> fp16 hi/lo
    ln_fused<0><<<BT, 256>>>(x, ln1_w, c, nullptr, p_aHi, p_aLo);
    split2_kernel<<<(3 * DMODEL * DMODEL / 4 + 255) / 256, 256>>>(w_qkv, p_wHi, p_wLo, 3 * DMODEL * DMODEL / 4);

    // 2) qkv = h @ w_qkv^T (3-term, pre-router precision)
    hmma_gemm<3, 3, 0><<<dim3(24, 32), 128, SMEM3>>>(p_aHi, p_aLo, p_wHi, p_wLo, 0, nullptr, nullptr, nullptr,
                                                     nullptr, nullptr, p_qkvHi, p_qkvLo, 3072, 1024);

    // 3) causal attention (3-term)
    attn_hmma<<<dim3(16, 64), 128, AT_SMEM>>>(p_qkvHi, p_qkvLo, p_aHi, p_aLo);

    // 4) x2 = x + o @ w_proj^T (3-term)
    split2_kernel<<<(DMODEL * DMODEL / 4 + 255) / 256, 256>>>(w_proj, p_wHi, p_wLo, DMODEL * DMODEL / 4);
    hmma_gemm<1, 3, 0><<<dim3(8, 32), 128, SMEM3>>>(p_aHi, p_aLo, p_wHi, p_wLo, 0, nullptr, nullptr, nullptr,
                                                    p_x2, x, nullptr, nullptr, 1024, 1024);

    // 5) xn = LN2(x2) -> fp32 base written DIRECTLY into out + fp16 hi/lo
    ln_fused<1><<<BT, 256>>>(p_x2, ln2_w, nullptr, out, p_aHi, p_aLo);

    // 6) router reads out (== xn, before fc2 modifies it) + slot tables
    router_kernel<<<BT, 256>>>(out, router_w, p_eidx, p_wts);
    build_kernel<<<1, 256>>>(p_eidx, p_wts, p_stok, p_sw, p_te);

    // join: expert weights ready before fc1
    cudaStreamWaitEvent(0, evJ, 0);

    // 7) fc1: hid = gelu(gather(xn) @ w1[e]^T) — 1-term, NSTG=6, in-kernel gather
    hmma_gemm<5, 1, 1><<<dim3(32, NTILES), 128, SMEM1>>>(p_aHi, nullptr, p_w1, nullptr,
                                                         (size_t)FF * DMODEL, p_te, p_stok, nullptr,
                                                         nullptr, nullptr, p_hid, nullptr, FF, 1024);

    // 8) fc2: out += w_slot * (hid @ w2[e]^T) — scatter epilogue, combine fused away
    hmma_gemm<4, 1, 0><<<dim3(8, NTILES), 128, SMEM1>>>(p_hid, nullptr, p_w2, nullptr,
                                                        (size_t)DMODEL * FF, p_te, p_stok, p_sw,
                                                        out, nullptr, nullptr, nullptr, 1024, 4096);
}